// round 1
// baseline (speedup 1.0000x reference)
#include <cuda_runtime.h>
#include <math.h>

#define Bb 32
#define Ll 1024
#define Dd 768

#define BM 128
#define BN 128
#define BK 16
#define TM 8
#define TN 8
// 256 threads per GEMM block

// Scratch (device globals; no allocation allowed)
__device__ float g_att[(size_t)Bb * Ll * Ll];   // att, then overwritten with w1
__device__ float g_w2 [(size_t)Bb * Ll * Ll];   // w2
__device__ float g_rowmax[Bb * Ll];
__device__ float g_rowsinv[Bb * Ll];
__device__ float g_colmax[Bb * Ll];
__device__ float g_colsinv[Bb * Ll];

// ---------------------------------------------------------------------------
// Shared-memory tile loaders.
// smem layout: S[k][x] with stride 128 floats (k-major), k in [0,16), x in [0,128)
// ---------------------------------------------------------------------------

// Operand stored [row=x][col=k], k contiguous (ld = row stride). Transpose into S[k][x].
__device__ __forceinline__ void load_trans(float* S, const float* __restrict__ G,
                                           int ld, int tid) {
#pragma unroll
    for (int it = 0; it < 2; ++it) {
        int q   = tid + it * 256;   // 0..511
        int row = q >> 2;           // 0..127
        int c4  = (q & 3) << 2;     // 0,4,8,12
        float4 v = *(const float4*)&G[(size_t)row * ld + c4];
        S[(c4 + 0) * 128 + row] = v.x;
        S[(c4 + 1) * 128 + row] = v.y;
        S[(c4 + 2) * 128 + row] = v.z;
        S[(c4 + 3) * 128 + row] = v.w;
    }
}

// Operand stored [row=k][col=x], x contiguous (ld = row stride). Direct copy.
__device__ __forceinline__ void load_direct(float* S, const float* __restrict__ G,
                                            int ld, int tid) {
#pragma unroll
    for (int it = 0; it < 2; ++it) {
        int q  = tid + it * 256;    // 0..511
        int kr = q >> 5;            // 0..15
        int c4 = (q & 31) << 2;     // 0..124
        *(float4*)&S[kr * 128 + c4] = *(const float4*)&G[(size_t)kr * ld + c4];
    }
}

__device__ __forceinline__ void micro_fma(const float* __restrict__ As,
                                          const float* __restrict__ Bs,
                                          float acc[TM][TN], int tm8, int tn8) {
#pragma unroll
    for (int k = 0; k < BK; ++k) {
        float a[TM], bv[TN];
        *(float4*)&a[0]  = *(const float4*)&As[k * BM + tm8];
        *(float4*)&a[4]  = *(const float4*)&As[k * BM + tm8 + 4];
        *(float4*)&bv[0] = *(const float4*)&Bs[k * BN + tn8];
        *(float4*)&bv[4] = *(const float4*)&Bs[k * BN + tn8 + 4];
#pragma unroll
        for (int i = 0; i < TM; ++i)
#pragma unroll
            for (int j = 0; j < TN; ++j)
                acc[i][j] = fmaf(a[i], bv[j], acc[i][j]);
    }
}

// ---------------------------------------------------------------------------
// Kernel 1: att[b,i,j] = dot(in1[b,i,:], in2[b,j,:])   (NT GEMM, K=768)
// ---------------------------------------------------------------------------
__global__ __launch_bounds__(256, 2)
void k_att(const float* __restrict__ in1, const float* __restrict__ in2) {
    __shared__ float As[BK * BM];
    __shared__ float Bs[BK * BN];
    int b  = blockIdx.z;
    int m0 = blockIdx.y * BM;   // i
    int n0 = blockIdx.x * BN;   // j
    const float* A = in1 + (size_t)b * Ll * Dd + (size_t)m0 * Dd;
    const float* Bg = in2 + (size_t)b * Ll * Dd + (size_t)n0 * Dd;

    int tid = threadIdx.x;
    int tm8 = (tid & 15) * TM;
    int tn8 = (tid >> 4) * TN;
    float acc[TM][TN] = {};

    for (int k0 = 0; k0 < Dd; k0 += BK) {
        load_trans(As, A + k0, Dd, tid);
        load_trans(Bs, Bg + k0, Dd, tid);
        __syncthreads();
        micro_fma(As, Bs, acc, tm8, tn8);
        __syncthreads();
    }

    float* C = g_att + (size_t)b * Ll * Ll;
#pragma unroll
    for (int i = 0; i < TM; ++i)
#pragma unroll
        for (int j = 0; j < TN; j += 4)
            *(float4*)&C[(size_t)(m0 + tm8 + i) * Ll + n0 + tn8 + j] =
                *(float4*)&acc[i][j];
}

// ---------------------------------------------------------------------------
// Kernel 2: per-row (over j) max + 1/sum(exp)
// ---------------------------------------------------------------------------
__global__ void k_rowstats() {
    int r = blockIdx.x;                       // b*L + i
    const float* p = g_att + (size_t)r * Ll;
    int tid = threadIdx.x;                    // 256
    float4 v = ((const float4*)p)[tid];

    float m = fmaxf(fmaxf(v.x, v.y), fmaxf(v.z, v.w));
#pragma unroll
    for (int o = 16; o; o >>= 1) m = fmaxf(m, __shfl_xor_sync(~0u, m, o));
    __shared__ float redm[8], reds[8];
    if ((tid & 31) == 0) redm[tid >> 5] = m;
    __syncthreads();
    float bm = redm[0];
#pragma unroll
    for (int w = 1; w < 8; ++w) bm = fmaxf(bm, redm[w]);

    float s = __expf(v.x - bm) + __expf(v.y - bm) + __expf(v.z - bm) + __expf(v.w - bm);
#pragma unroll
    for (int o = 16; o; o >>= 1) s += __shfl_xor_sync(~0u, s, o);
    if ((tid & 31) == 0) reds[tid >> 5] = s;
    __syncthreads();
    if (tid == 0) {
        float t = 0.f;
#pragma unroll
        for (int w = 0; w < 8; ++w) t += reds[w];
        g_rowmax[r]  = bm;
        g_rowsinv[r] = 1.f / t;
    }
}

// ---------------------------------------------------------------------------
// Kernel 3: per-column (over i) max + 1/sum(exp), online, coalesced across j
// ---------------------------------------------------------------------------
__global__ void k_colstats() {
    int b = blockIdx.y;
    int j = blockIdx.x * 128 + threadIdx.x;
    const float* p = g_att + (size_t)b * Ll * Ll + j;

    float m = p[0];
    float s = 1.f;
    for (int i = 1; i < Ll; ++i) {
        float v = p[(size_t)i * Ll];
        if (v > m) {
            s = s * __expf(m - v) + 1.f;
            m = v;
        } else {
            s += __expf(v - m);
        }
    }
    g_colmax[b * Ll + j]  = m;
    g_colsinv[b * Ll + j] = 1.f / s;
}

// ---------------------------------------------------------------------------
// Kernel 4: w2 = rowsoftmax(att) -> g_w2 ; w1 = colsoftmax(att) -> g_att
// ---------------------------------------------------------------------------
__global__ void k_norm() {
    size_t idx4 = (size_t)blockIdx.x * 256 + threadIdx.x;   // float4 index
    size_t base = idx4 * 4;
    int b   = (int)(base >> 20);
    int rem = (int)(base & (Ll * Ll - 1));
    int i   = rem >> 10;
    int j   = rem & (Ll - 1);

    float4 a  = *(const float4*)&g_att[base];
    float  rm = g_rowmax[b * Ll + i];
    float  rs = g_rowsinv[b * Ll + i];
    float4 cm = *(const float4*)&g_colmax[b * Ll + j];
    float4 cs = *(const float4*)&g_colsinv[b * Ll + j];

    float4 w2, w1;
    w2.x = __expf(a.x - rm) * rs;  w2.y = __expf(a.y - rm) * rs;
    w2.z = __expf(a.z - rm) * rs;  w2.w = __expf(a.w - rm) * rs;
    w1.x = __expf(a.x - cm.x) * cs.x;  w1.y = __expf(a.y - cm.y) * cs.y;
    w1.z = __expf(a.z - cm.z) * cs.z;  w1.w = __expf(a.w - cm.w) * cs.w;

    *(float4*)&g_w2[base]  = w2;
    *(float4*)&g_att[base] = w1;   // att buffer now holds w1
}

// ---------------------------------------------------------------------------
// Kernel 5: outA[b,j,d] = sum_i w1[b,i,j] * in1[b,i,d]   (w1^T @ in1)
// w1 stored [i][j] (j contiguous) -> A tile is [k=i][m=j]: direct load
// ---------------------------------------------------------------------------
__global__ __launch_bounds__(256, 2)
void k_outA(const float* __restrict__ in1, float* __restrict__ out) {
    __shared__ float As[BK * BM];
    __shared__ float Bs[BK * BN];
    int b  = blockIdx.z;
    int m0 = blockIdx.y * BM;   // j
    int n0 = blockIdx.x * BN;   // d
    const float* Ag = g_att + (size_t)b * Ll * Ll + m0;          // [i][j]
    const float* Bg = in1   + (size_t)b * Ll * Dd + n0;          // [i][d]

    int tid = threadIdx.x;
    int tm8 = (tid & 15) * TM;
    int tn8 = (tid >> 4) * TN;
    float acc[TM][TN] = {};

    for (int k0 = 0; k0 < Ll; k0 += BK) {
        load_direct(As, Ag + (size_t)k0 * Ll, Ll, tid);
        load_direct(Bs, Bg + (size_t)k0 * Dd, Dd, tid);
        __syncthreads();
        micro_fma(As, Bs, acc, tm8, tn8);
        __syncthreads();
    }

    float* C = out + (size_t)b * Ll * Dd;
#pragma unroll
    for (int i = 0; i < TM; ++i)
#pragma unroll
        for (int j = 0; j < TN; j += 4)
            *(float4*)&C[(size_t)(m0 + tm8 + i) * Dd + n0 + tn8 + j] =
                *(float4*)&acc[i][j];
}

// ---------------------------------------------------------------------------
// Kernel 6: outB[b,i,d] = sum_j w2[b,i,j] * in2[b,j,d]   (w2 @ in2)
// w2 stored [i][j] (j=k contiguous) -> A tile is [m=i][k=j]: transpose load
// ---------------------------------------------------------------------------
__global__ __launch_bounds__(256, 2)
void k_outB(const float* __restrict__ in2, float* __restrict__ out) {
    __shared__ float As[BK * BM];
    __shared__ float Bs[BK * BN];
    int b  = blockIdx.z;
    int m0 = blockIdx.y * BM;   // i
    int n0 = blockIdx.x * BN;   // d
    const float* Ag = g_w2 + (size_t)b * Ll * Ll + (size_t)m0 * Ll; // [i][j]
    const float* Bg = in2  + (size_t)b * Ll * Dd + n0;              // [j][d]

    int tid = threadIdx.x;
    int tm8 = (tid & 15) * TM;
    int tn8 = (tid >> 4) * TN;
    float acc[TM][TN] = {};

    for (int k0 = 0; k0 < Ll; k0 += BK) {
        load_trans(As, Ag + k0, Ll, tid);
        load_direct(Bs, Bg + (size_t)k0 * Dd, Dd, tid);
        __syncthreads();
        micro_fma(As, Bs, acc, tm8, tn8);
        __syncthreads();
    }

    float* C = out + (size_t)b * Ll * Dd;
#pragma unroll
    for (int i = 0; i < TM; ++i)
#pragma unroll
        for (int j = 0; j < TN; j += 4)
            *(float4*)&C[(size_t)(m0 + tm8 + i) * Dd + n0 + tn8 + j] =
                *(float4*)&acc[i][j];
}

// ---------------------------------------------------------------------------
extern "C" void kernel_launch(void* const* d_in, const int* in_sizes, int n_in,
                              void* d_out, int out_size) {
    const float* in1 = (const float*)d_in[0];
    const float* in2 = (const float*)d_in[1];
    float* out = (float*)d_out;

    // 1) scores
    k_att<<<dim3(Ll / BN, Ll / BM, Bb), 256>>>(in1, in2);
    // 2) softmax stats
    k_rowstats<<<Bb * Ll, 256>>>();
    k_colstats<<<dim3(Ll / 128, Bb), 128>>>();
    // 3) normalize -> w1 (in g_att), w2 (in g_w2)
    k_norm<<<(Bb * Ll * Ll) / (256 * 4), 256>>>();
    // 4) outputs: first half = in1_aligned (outA), second half = in2_aligned (outB)
    k_outA<<<dim3(Dd / BN, Ll / BM, Bb), 256>>>(in1, out);
    k_outB<<<dim3(Dd / BN, Ll / BM, Bb), 256>>>(in2, out + (size_t)Bb * Ll * Dd);
}

// round 3
// speedup vs baseline: 1.7891x; 1.7891x over previous
#include <cuda_runtime.h>
#include <cuda_bf16.h>
#include <mma.h>
#include <cstdint>
#include <math.h>

using namespace nvcuda;

#define Bb 32
#define Ll 1024
#define Dd 768

// ---------------------------------------------------------------------------
// Scratch (device globals; no allocation allowed)
// ---------------------------------------------------------------------------
__device__ float g_att [(size_t)Bb * Ll * Ll];   // att[i][j]
__device__ float g_att2[(size_t)Bb * Ll * Ll];   // att^T  [j][i]

__device__ __nv_bfloat16 g_in1hi[(size_t)Bb * Ll * Dd];
__device__ __nv_bfloat16 g_in1lo[(size_t)Bb * Ll * Dd];
__device__ __nv_bfloat16 g_in2hi[(size_t)Bb * Ll * Dd];
__device__ __nv_bfloat16 g_in2lo[(size_t)Bb * Ll * Dd];

__device__ __nv_bfloat16 g_w2hi [(size_t)Bb * Ll * Ll];   // row-softmax(att)  [i][j]
__device__ __nv_bfloat16 g_w2lo [(size_t)Bb * Ll * Ll];
__device__ __nv_bfloat16 g_w1thi[(size_t)Bb * Ll * Ll];   // row-softmax(att2) [j][i]
__device__ __nv_bfloat16 g_w1tlo[(size_t)Bb * Ll * Ll];

__device__ float g_rmax1 [Bb * Ll];
__device__ float g_rsinv1[Bb * Ll];
__device__ float g_rmax2 [Bb * Ll];
__device__ float g_rsinv2[Bb * Ll];

struct alignas(8) BF4 { __nv_bfloat16 v[4]; };

__device__ __forceinline__ BF4 split4(const float* vv, BF4& lo) {
    BF4 hi;
#pragma unroll
    for (int k = 0; k < 4; ++k) {
        hi.v[k] = __float2bfloat16(vv[k]);
        lo.v[k] = __float2bfloat16(vv[k] - __bfloat162float(hi.v[k]));
    }
    return hi;
}

// ---------------------------------------------------------------------------
// Elementwise split fp32 -> bf16 hi/lo
// ---------------------------------------------------------------------------
__global__ __launch_bounds__(256)
void k_split(const float* __restrict__ src,
             __nv_bfloat16* __restrict__ hi, __nv_bfloat16* __restrict__ lo) {
    size_t idx4 = (size_t)blockIdx.x * 256 + threadIdx.x;
    size_t base = idx4 * 4;
    float4 v = *(const float4*)&src[base];
    float vv[4] = {v.x, v.y, v.z, v.w};
    BF4 l4; BF4 h4 = split4(vv, l4);
    *(BF4*)&hi[base] = h4;
    *(BF4*)&lo[base] = l4;
}

// ---------------------------------------------------------------------------
// WMMA bf16x3 GEMM: C[M,N] = A @ OpB, fp32 accumulate in tensor cores.
//   A   : [M,K] row-major (lda), split hi/lo
//   B_COL=true : B = [N,K] rows (col_major fragments)  -> C = A @ B^T
//   B_COL=false: B = [K,N] rows (row_major fragments)  -> C = A @ B
// CTA tile 128x128, K-chunk 64, 8 warps in 4(M) x 2(N), warp tile 32x64.
// WRITE_T additionally writes C^T via an SMEM-staged transpose.
// ---------------------------------------------------------------------------
#define APITCH 72     // bf16 elems per smem row (64 + 8 pad)
#define BPITCH_ROW 136

template <bool B_COL, bool WRITE_T>
__global__ __launch_bounds__(256)
void gemmw(const __nv_bfloat16* __restrict__ Ahi, const __nv_bfloat16* __restrict__ Alo,
           const __nv_bfloat16* __restrict__ Bhi, const __nv_bfloat16* __restrict__ Blo,
           int lda, int ldb, int K,
           float* __restrict__ C, int ldc,
           size_t sA, size_t sB, size_t sC,
           float* __restrict__ CT, int ldct, size_t sCT) {
    extern __shared__ char sm[];
    __nv_bfloat16* sAhi = (__nv_bfloat16*)(sm);
    __nv_bfloat16* sAlo = (__nv_bfloat16*)(sm + 18432);
    __nv_bfloat16* sBhi = (__nv_bfloat16*)(sm + 36864);
    __nv_bfloat16* sBlo = (__nv_bfloat16*)(sm + 55296);

    int tid  = threadIdx.x;
    int wid  = tid >> 5;
    int wm   = wid & 3;         // 0..3 -> M offset
    int wn   = wid >> 2;        // 0..1 -> N offset
    int b  = blockIdx.z;
    int m0 = blockIdx.y * 128;
    int n0 = blockIdx.x * 128;

    const __nv_bfloat16* Ah = Ahi + (size_t)b * sA;
    const __nv_bfloat16* Al = Alo + (size_t)b * sA;
    const __nv_bfloat16* Bh = Bhi + (size_t)b * sB;
    const __nv_bfloat16* Bl = Blo + (size_t)b * sB;

    wmma::fragment<wmma::accumulator, 16, 16, 16, float> acc[2][4];
#pragma unroll
    for (int i = 0; i < 2; ++i)
#pragma unroll
        for (int j = 0; j < 4; ++j)
            wmma::fill_fragment(acc[i][j], 0.0f);

    for (int k0 = 0; k0 < K; k0 += 64) {
        // --- A tiles: 128 rows x 64 bf16 (8 uint4 per row) ---
#pragma unroll
        for (int it = 0; it < 4; ++it) {
            int q  = tid + it * 256;            // 0..1023
            int r  = q >> 3;                    // 0..127
            int c8 = (q & 7) << 3;              // 0..56
            int so = r * APITCH + c8;
            *(uint4*)&sAhi[so] = *(const uint4*)(Ah + (size_t)(m0 + r) * lda + k0 + c8);
            *(uint4*)&sAlo[so] = *(const uint4*)(Al + (size_t)(m0 + r) * lda + k0 + c8);
        }
        // --- B tiles ---
        if (B_COL) {
            // [n][k] rows: 128 rows x 64 bf16
#pragma unroll
            for (int it = 0; it < 4; ++it) {
                int q  = tid + it * 256;
                int r  = q >> 3;
                int c8 = (q & 7) << 3;
                int so = r * APITCH + c8;
                *(uint4*)&sBhi[so] = *(const uint4*)(Bh + (size_t)(n0 + r) * ldb + k0 + c8);
                *(uint4*)&sBlo[so] = *(const uint4*)(Bl + (size_t)(n0 + r) * ldb + k0 + c8);
            }
        } else {
            // [k][n] rows: 64 rows x 128 bf16 (16 uint4 per row)
#pragma unroll
            for (int it = 0; it < 4; ++it) {
                int q  = tid + it * 256;
                int r  = q >> 4;                // 0..63
                int c8 = (q & 15) << 3;         // 0..120
                int so = r * BPITCH_ROW + c8;
                *(uint4*)&sBhi[so] = *(const uint4*)(Bh + (size_t)(k0 + r) * ldb + n0 + c8);
                *(uint4*)&sBlo[so] = *(const uint4*)(Bl + (size_t)(k0 + r) * ldb + n0 + c8);
            }
        }
        __syncthreads();

#pragma unroll
        for (int ks = 0; ks < 4; ++ks) {
            wmma::fragment<wmma::matrix_a, 16, 16, 16, __nv_bfloat16, wmma::row_major> ah[2], al[2];
#pragma unroll
            for (int fi = 0; fi < 2; ++fi) {
                int ro = (wm * 32 + fi * 16) * APITCH + ks * 16;
                wmma::load_matrix_sync(ah[fi], &sAhi[ro], APITCH);
                wmma::load_matrix_sync(al[fi], &sAlo[ro], APITCH);
            }
            if (B_COL) {
                wmma::fragment<wmma::matrix_b, 16, 16, 16, __nv_bfloat16, wmma::col_major> bh[4], bl[4];
#pragma unroll
                for (int fj = 0; fj < 4; ++fj) {
                    int ro = (wn * 64 + fj * 16) * APITCH + ks * 16;
                    wmma::load_matrix_sync(bh[fj], &sBhi[ro], APITCH);
                    wmma::load_matrix_sync(bl[fj], &sBlo[ro], APITCH);
                }
#pragma unroll
                for (int fi = 0; fi < 2; ++fi)
#pragma unroll
                    for (int fj = 0; fj < 4; ++fj) {
                        wmma::mma_sync(acc[fi][fj], ah[fi], bh[fj], acc[fi][fj]);
                        wmma::mma_sync(acc[fi][fj], al[fi], bh[fj], acc[fi][fj]);
                        wmma::mma_sync(acc[fi][fj], ah[fi], bl[fj], acc[fi][fj]);
                    }
            } else {
                wmma::fragment<wmma::matrix_b, 16, 16, 16, __nv_bfloat16, wmma::row_major> bh[4], bl[4];
#pragma unroll
                for (int fj = 0; fj < 4; ++fj) {
                    int ro = (ks * 16) * BPITCH_ROW + wn * 64 + fj * 16;
                    wmma::load_matrix_sync(bh[fj], &sBhi[ro], BPITCH_ROW);
                    wmma::load_matrix_sync(bl[fj], &sBlo[ro], BPITCH_ROW);
                }
#pragma unroll
                for (int fi = 0; fi < 2; ++fi)
#pragma unroll
                    for (int fj = 0; fj < 4; ++fj) {
                        wmma::mma_sync(acc[fi][fj], ah[fi], bh[fj], acc[fi][fj]);
                        wmma::mma_sync(acc[fi][fj], al[fi], bh[fj], acc[fi][fj]);
                        wmma::mma_sync(acc[fi][fj], ah[fi], bl[fj], acc[fi][fj]);
                    }
            }
        }
        __syncthreads();
    }

    // --- Epilogue: C (direct), optionally C^T via smem transpose ---
    float* Cb = C + (size_t)b * sC;
#pragma unroll
    for (int fi = 0; fi < 2; ++fi)
#pragma unroll
        for (int fj = 0; fj < 4; ++fj) {
            int gr = m0 + wm * 32 + fi * 16;
            int gc = n0 + wn * 64 + fj * 16;
            wmma::store_matrix_sync(&Cb[(size_t)gr * ldc + gc], acc[fi][fj], ldc,
                                    wmma::mem_row_major);
        }

    if (WRITE_T) {
        float* Sf = (float*)sm;    // 128 x 132 fp32 staging (67584B <= 73728B)
#pragma unroll
        for (int fi = 0; fi < 2; ++fi)
#pragma unroll
            for (int fj = 0; fj < 4; ++fj) {
                int lr = wm * 32 + fi * 16;
                int lc = wn * 64 + fj * 16;
                wmma::store_matrix_sync(&Sf[lr * 132 + lc], acc[fi][fj], 132,
                                        wmma::mem_row_major);
            }
        __syncthreads();
        float* CTb = CT + (size_t)b * sCT;
#pragma unroll 4
        for (int it = 0; it < 64; ++it) {
            int q  = tid + it * 256;
            int ii = q & 127;
            int jj = q >> 7;
            CTb[(size_t)(n0 + jj) * ldct + m0 + ii] = Sf[ii * 132 + jj];
        }
    }
}

// ---------------------------------------------------------------------------
// Row stats: per-row max + 1/sum(exp) over 1024 contiguous elems
// ---------------------------------------------------------------------------
__global__ __launch_bounds__(256)
void k_rowstats(const float* __restrict__ att,
                float* __restrict__ omax, float* __restrict__ osinv) {
    int r = blockIdx.x;
    const float* p = att + (size_t)r * Ll;
    int tid = threadIdx.x;
    float4 v = ((const float4*)p)[tid];

    float m = fmaxf(fmaxf(v.x, v.y), fmaxf(v.z, v.w));
#pragma unroll
    for (int o = 16; o; o >>= 1) m = fmaxf(m, __shfl_xor_sync(~0u, m, o));
    __shared__ float redm[8], reds[8];
    if ((tid & 31) == 0) redm[tid >> 5] = m;
    __syncthreads();
    float bm = redm[0];
#pragma unroll
    for (int w = 1; w < 8; ++w) bm = fmaxf(bm, redm[w]);

    float s = __expf(v.x - bm) + __expf(v.y - bm) + __expf(v.z - bm) + __expf(v.w - bm);
#pragma unroll
    for (int o = 16; o; o >>= 1) s += __shfl_xor_sync(~0u, s, o);
    if ((tid & 31) == 0) reds[tid >> 5] = s;
    __syncthreads();
    if (tid == 0) {
        float t = 0.f;
#pragma unroll
        for (int w = 0; w < 8; ++w) t += reds[w];
        omax[r]  = bm;
        osinv[r] = 1.f / t;
    }
}

// ---------------------------------------------------------------------------
// Normalize + split to bf16 hi/lo: w = exp(a - rowmax) * rowsinv
// ---------------------------------------------------------------------------
__global__ __launch_bounds__(256)
void k_normsplit(const float* __restrict__ att,
                 const float* __restrict__ rmax, const float* __restrict__ rsinv,
                 __nv_bfloat16* __restrict__ whi, __nv_bfloat16* __restrict__ wlo) {
    size_t idx4 = (size_t)blockIdx.x * 256 + threadIdx.x;
    size_t base = idx4 * 4;
    int row = (int)(base >> 10);

    float4 a = *(const float4*)&att[base];
    float rm = rmax[row];
    float rs = rsinv[row];
    float w[4];
    w[0] = __expf(a.x - rm) * rs;
    w[1] = __expf(a.y - rm) * rs;
    w[2] = __expf(a.z - rm) * rs;
    w[3] = __expf(a.w - rm) * rs;
    BF4 l4; BF4 h4 = split4(w, l4);
    *(BF4*)&whi[base] = h4;
    *(BF4*)&wlo[base] = l4;
}

// ---------------------------------------------------------------------------
extern "C" void kernel_launch(void* const* d_in, const int* in_sizes, int n_in,
                              void* d_out, int out_size) {
    const float* in1 = (const float*)d_in[0];
    const float* in2 = (const float*)d_in[1];
    float* out = (float*)d_out;

    const int SMEM_BYTES = 73728;
    cudaFuncSetAttribute(gemmw<true,  true >, cudaFuncAttributeMaxDynamicSharedMemorySize, SMEM_BYTES);
    cudaFuncSetAttribute(gemmw<false, false>, cudaFuncAttributeMaxDynamicSharedMemorySize, SMEM_BYTES);

    float *att, *att2, *rmax1, *rsinv1, *rmax2, *rsinv2;
    __nv_bfloat16 *i1h, *i1l, *i2h, *i2l, *w2h, *w2l, *w1th, *w1tl;
    cudaGetSymbolAddress((void**)&att,  g_att);
    cudaGetSymbolAddress((void**)&att2, g_att2);
    cudaGetSymbolAddress((void**)&i1h,  g_in1hi);
    cudaGetSymbolAddress((void**)&i1l,  g_in1lo);
    cudaGetSymbolAddress((void**)&i2h,  g_in2hi);
    cudaGetSymbolAddress((void**)&i2l,  g_in2lo);
    cudaGetSymbolAddress((void**)&w2h,  g_w2hi);
    cudaGetSymbolAddress((void**)&w2l,  g_w2lo);
    cudaGetSymbolAddress((void**)&w1th, g_w1thi);
    cudaGetSymbolAddress((void**)&w1tl, g_w1tlo);
    cudaGetSymbolAddress((void**)&rmax1,  g_rmax1);
    cudaGetSymbolAddress((void**)&rsinv1, g_rsinv1);
    cudaGetSymbolAddress((void**)&rmax2,  g_rmax2);
    cudaGetSymbolAddress((void**)&rsinv2, g_rsinv2);

    // 1) split both inputs to bf16 hi/lo
    int sblk = (int)(((size_t)Bb * Ll * Dd) / (256 * 4));
    k_split<<<sblk, 256>>>(in1, i1h, i1l);
    k_split<<<sblk, 256>>>(in2, i2h, i2l);

    // 2) scores: att = in1 @ in2^T (K=768); also writes att2 = att^T
    gemmw<true, true><<<dim3(Ll / 128, Ll / 128, Bb), 256, SMEM_BYTES>>>(
        i1h, i1l, i2h, i2l, Dd, Dd, Dd,
        att, Ll, (size_t)Ll * Dd, (size_t)Ll * Dd, (size_t)Ll * Ll,
        att2, Ll, (size_t)Ll * Ll);

    // 3) row stats on att (-> w2) and att2 (-> w1^T)
    k_rowstats<<<Bb * Ll, 256>>>(att,  rmax1, rsinv1);
    k_rowstats<<<Bb * Ll, 256>>>(att2, rmax2, rsinv2);

    // 4) normalize + split
    int nblk = (int)(((size_t)Bb * Ll * Ll) / (256 * 4));
    k_normsplit<<<nblk, 256>>>(att,  rmax1, rsinv1, w2h,  w2l);
    k_normsplit<<<nblk, 256>>>(att2, rmax2, rsinv2, w1th, w1tl);

    // 5) outA[b,j,d] = sum_i w1t[j,i] * in1[i,d]   (A=w1t, B=in1 row-major)
    gemmw<false, false><<<dim3(Dd / 128, Ll / 128, Bb), 256, SMEM_BYTES>>>(
        w1th, w1tl, i1h, i1l, Ll, Dd, Ll,
        out, Dd, (size_t)Ll * Ll, (size_t)Ll * Dd, (size_t)Ll * Dd,
        nullptr, 0, 0);

    // 6) outB[b,i,d] = sum_j w2[i,j] * in2[j,d]    (A=w2, B=in2 row-major)
    gemmw<false, false><<<dim3(Dd / 128, Ll / 128, Bb), 256, SMEM_BYTES>>>(
        w2h, w2l, i2h, i2l, Ll, Dd, Ll,
        out + (size_t)Bb * Ll * Dd, Dd, (size_t)Ll * Ll, (size_t)Ll * Dd, (size_t)Ll * Dd,
        nullptr, 0, 0);
}

// round 5
// speedup vs baseline: 2.2067x; 1.2334x over previous
#include <cuda_runtime.h>
#include <cuda_bf16.h>
#include <mma.h>
#include <cstdint>
#include <math.h>

using namespace nvcuda;

#define Bb 32
#define Ll 1024
#define Dd 768

// ---------------------------------------------------------------------------
// Scratch (device globals; no allocation allowed)
// ---------------------------------------------------------------------------
__device__ float g_att [(size_t)Bb * Ll * Ll];   // att[i][j]
__device__ float g_att2[(size_t)Bb * Ll * Ll];   // att^T  [j][i]

__device__ __nv_bfloat16 g_in1hi[(size_t)Bb * Ll * Dd];
__device__ __nv_bfloat16 g_in1lo[(size_t)Bb * Ll * Dd];
__device__ __nv_bfloat16 g_in2hi[(size_t)Bb * Ll * Dd];
__device__ __nv_bfloat16 g_in2lo[(size_t)Bb * Ll * Dd];

__device__ __nv_bfloat16 g_w2hi [(size_t)Bb * Ll * Ll];   // row-softmax(att)  [i][j]
__device__ __nv_bfloat16 g_w2lo [(size_t)Bb * Ll * Ll];
__device__ __nv_bfloat16 g_w1thi[(size_t)Bb * Ll * Ll];   // row-softmax(att2) [j][i]
__device__ __nv_bfloat16 g_w1tlo[(size_t)Bb * Ll * Ll];

__device__ float g_rmax1 [Bb * Ll];
__device__ float g_rsinv1[Bb * Ll];
__device__ float g_rmax2 [Bb * Ll];
__device__ float g_rsinv2[Bb * Ll];

struct alignas(8) BF4 { __nv_bfloat16 v[4]; };

__device__ __forceinline__ BF4 split4(const float* vv, BF4& lo) {
    BF4 hi;
#pragma unroll
    for (int k = 0; k < 4; ++k) {
        hi.v[k] = __float2bfloat16(vv[k]);
        lo.v[k] = __float2bfloat16(vv[k] - __bfloat162float(hi.v[k]));
    }
    return hi;
}

__device__ __forceinline__ uint32_t smem_u32(const void* p) {
    uint32_t a;
    asm("{ .reg .u64 t; cvta.to.shared.u64 t, %1; cvt.u32.u64 %0, t; }"
        : "=r"(a) : "l"(p));
    return a;
}

__device__ __forceinline__ void cp16(uint32_t dst, const void* src) {
    asm volatile("cp.async.cg.shared.global [%0], [%1], 16;" :: "r"(dst), "l"(src));
}
#define CP_COMMIT() asm volatile("cp.async.commit_group;" ::: "memory")
#define CP_WAIT(n)  asm volatile("cp.async.wait_group %0;" :: "n"(n) : "memory")

// ---------------------------------------------------------------------------
// Elementwise split fp32 -> bf16 hi/lo
// ---------------------------------------------------------------------------
__global__ __launch_bounds__(256)
void k_split(const float* __restrict__ src,
             __nv_bfloat16* __restrict__ hi, __nv_bfloat16* __restrict__ lo) {
    size_t idx4 = (size_t)blockIdx.x * 256 + threadIdx.x;
    size_t base = idx4 * 4;
    float4 v = *(const float4*)&src[base];
    float vv[4] = {v.x, v.y, v.z, v.w};
    BF4 l4; BF4 h4 = split4(vv, l4);
    *(BF4*)&hi[base] = h4;
    *(BF4*)&lo[base] = l4;
}

// ---------------------------------------------------------------------------
// Pipelined WMMA bf16x3 GEMM: C = A @ OpB, fp32 accum, cp.async double buffer.
//   A: [M,K] row-major, hi/lo.  B_COL: B [N,K] (col_major frags) else [K,N].
// CTA 128x128, K-chunk 32, 2 stages. 8 warps = 4(M) x 2(N), warp tile 32x64.
// ---------------------------------------------------------------------------
#define KC 32
#define AP 40            // A/Bcol smem pitch in bf16 elems (80B rows)
#define BP 136           // Brow smem pitch in bf16 elems (272B rows)
#define A_TILE_B (128 * AP * 2)          // 10240 bytes
#define BROW_TILE_B (KC * BP * 2)        // 8704 bytes
#define STAGE_COL (4 * A_TILE_B)         // 40960
#define STAGE_ROW (2 * A_TILE_B + 2 * BROW_TILE_B)  // 37888

template <bool B_COL, bool WRITE_T>
__global__ __launch_bounds__(256, 2)
void gemmw(const __nv_bfloat16* __restrict__ Ahi, const __nv_bfloat16* __restrict__ Alo,
           const __nv_bfloat16* __restrict__ Bhi, const __nv_bfloat16* __restrict__ Blo,
           int lda, int ldb, int K,
           float* __restrict__ C, int ldc,
           size_t sA, size_t sB, size_t sC,
           float* __restrict__ CT, int ldct, size_t sCT) {
    extern __shared__ char sm[];
    const uint32_t sbase = smem_u32(sm);
    const int STAGE = B_COL ? STAGE_COL : STAGE_ROW;

    int tid = threadIdx.x;
    int wid = tid >> 5;
    int wm  = wid & 3;
    int wn  = wid >> 2;
    int b   = blockIdx.z;
    int m0  = blockIdx.y * 128;
    int n0  = blockIdx.x * 128;

    const __nv_bfloat16* Ah = Ahi + (size_t)b * sA + (size_t)m0 * lda;
    const __nv_bfloat16* Al = Alo + (size_t)b * sA + (size_t)m0 * lda;
    const __nv_bfloat16* Bh;
    const __nv_bfloat16* Bl;
    if (B_COL) { Bh = Bhi + (size_t)b * sB + (size_t)n0 * ldb;
                 Bl = Blo + (size_t)b * sB + (size_t)n0 * ldb; }
    else       { Bh = Bhi + (size_t)b * sB + n0;
                 Bl = Blo + (size_t)b * sB + n0; }

    // per-thread load coordinates
    int arow = tid >> 2;            // 0..63 (x2 halves -> 128 rows), KC cols
    int ac16 = (tid & 3) * 8;       // 0..24 bf16 (covers 32 = KC)
    int brow = tid >> 4;            // 0..15 (x2 halves -> 32 rows = KC)
    int bc16 = (tid & 15) * 8;      // 0..120 bf16 (covers 128 cols)

    auto load_stage = [&](int st, int k0) {
        uint32_t s = sbase + st * STAGE;
#pragma unroll
        for (int h = 0; h < 2; ++h) {
            int r = arow + h * 64;
            uint32_t d = s + r * (AP * 2) + ac16 * 2;
            cp16(d,            Ah + (size_t)r * lda + k0 + ac16);
            cp16(d + A_TILE_B, Al + (size_t)r * lda + k0 + ac16);
        }
        if (B_COL) {
#pragma unroll
            for (int h = 0; h < 2; ++h) {
                int r = arow + h * 64;
                uint32_t d = s + 2 * A_TILE_B + r * (AP * 2) + ac16 * 2;
                cp16(d,            Bh + (size_t)r * ldb + k0 + ac16);
                cp16(d + A_TILE_B, Bl + (size_t)r * ldb + k0 + ac16);
            }
        } else {
#pragma unroll
            for (int h = 0; h < 2; ++h) {
                int r = brow + h * 16;
                uint32_t d = s + 2 * A_TILE_B + r * (BP * 2) + bc16 * 2;
                cp16(d,               Bh + (size_t)(k0 + r) * ldb + bc16);
                cp16(d + BROW_TILE_B, Bl + (size_t)(k0 + r) * ldb + bc16);
            }
        }
    };

    wmma::fragment<wmma::accumulator, 16, 16, 16, float> acc[2][4];
#pragma unroll
    for (int i = 0; i < 2; ++i)
#pragma unroll
        for (int j = 0; j < 4; ++j)
            wmma::fill_fragment(acc[i][j], 0.0f);

    const int NK = K / KC;
    load_stage(0, 0);
    CP_COMMIT();

    for (int it = 0; it < NK; ++it) {
        if (it + 1 < NK) {
            load_stage((it + 1) & 1, (it + 1) * KC);
            CP_COMMIT();
            CP_WAIT(1);
        } else {
            CP_WAIT(0);
        }
        __syncthreads();

        const __nv_bfloat16* sAhi = (const __nv_bfloat16*)(sm + (it & 1) * STAGE);
        const __nv_bfloat16* sAlo = sAhi + A_TILE_B / 2;   // +A_TILE_B bytes
        const __nv_bfloat16* sBhi = sAhi + A_TILE_B;       // +2*A_TILE_B bytes
        const __nv_bfloat16* sBlo = B_COL ? (sBhi + A_TILE_B / 2)
                                          : (sBhi + BROW_TILE_B / 2);

#pragma unroll
        for (int ks = 0; ks < KC / 16; ++ks) {
            wmma::fragment<wmma::matrix_a, 16, 16, 16, __nv_bfloat16, wmma::row_major> ah[2], al[2];
#pragma unroll
            for (int fi = 0; fi < 2; ++fi) {
                int ro = (wm * 32 + fi * 16) * AP + ks * 16;
                wmma::load_matrix_sync(ah[fi], &sAhi[ro], AP);
                wmma::load_matrix_sync(al[fi], &sAlo[ro], AP);
            }
            if (B_COL) {
#pragma unroll
                for (int fj = 0; fj < 4; ++fj) {
                    wmma::fragment<wmma::matrix_b, 16, 16, 16, __nv_bfloat16, wmma::col_major> bh, bl;
                    int ro = (wn * 64 + fj * 16) * AP + ks * 16;
                    wmma::load_matrix_sync(bh, &sBhi[ro], AP);
                    wmma::load_matrix_sync(bl, &sBlo[ro], AP);
#pragma unroll
                    for (int fi = 0; fi < 2; ++fi) {
                        wmma::mma_sync(acc[fi][fj], ah[fi], bh, acc[fi][fj]);
                        wmma::mma_sync(acc[fi][fj], al[fi], bh, acc[fi][fj]);
                        wmma::mma_sync(acc[fi][fj], ah[fi], bl, acc[fi][fj]);
                    }
                }
            } else {
#pragma unroll
                for (int fj = 0; fj < 4; ++fj) {
                    wmma::fragment<wmma::matrix_b, 16, 16, 16, __nv_bfloat16, wmma::row_major> bh, bl;
                    int ro = (ks * 16) * BP + wn * 64 + fj * 16;
                    wmma::load_matrix_sync(bh, &sBhi[ro], BP);
                    wmma::load_matrix_sync(bl, &sBlo[ro], BP);
#pragma unroll
                    for (int fi = 0; fi < 2; ++fi) {
                        wmma::mma_sync(acc[fi][fj], ah[fi], bh, acc[fi][fj]);
                        wmma::mma_sync(acc[fi][fj], al[fi], bh, acc[fi][fj]);
                        wmma::mma_sync(acc[fi][fj], ah[fi], bl, acc[fi][fj]);
                    }
                }
            }
        }
        __syncthreads();
    }

    // --- Epilogue ---
    float* Cb = C + (size_t)b * sC;
#pragma unroll
    for (int fi = 0; fi < 2; ++fi)
#pragma unroll
        for (int fj = 0; fj < 4; ++fj) {
            int gr = m0 + wm * 32 + fi * 16;
            int gc = n0 + wn * 64 + fj * 16;
            wmma::store_matrix_sync(&Cb[(size_t)gr * ldc + gc], acc[fi][fj], ldc,
                                    wmma::mem_row_major);
        }

    if (WRITE_T) {
        float* Sf = (float*)sm;    // 128 x 132 fp32 staging = 67584B <= 81920B
#pragma unroll
        for (int fi = 0; fi < 2; ++fi)
#pragma unroll
            for (int fj = 0; fj < 4; ++fj) {
                int lr = wm * 32 + fi * 16;
                int lc = wn * 64 + fj * 16;
                wmma::store_matrix_sync(&Sf[lr * 132 + lc], acc[fi][fj], 132,
                                        wmma::mem_row_major);
            }
        __syncthreads();
        float* CTb = CT + (size_t)b * sCT;
#pragma unroll 4
        for (int it = 0; it < 64; ++it) {
            int q  = tid + it * 256;
            int ii = q & 127;
            int jj = q >> 7;
            CTb[(size_t)(n0 + jj) * ldct + m0 + ii] = Sf[ii * 132 + jj];
        }
    }
}

// ---------------------------------------------------------------------------
// Fused row stats for att and att2 (blockIdx.y selects source)
// ---------------------------------------------------------------------------
__global__ __launch_bounds__(256)
void k_rowstats2(const float* __restrict__ att, const float* __restrict__ att2,
                 float* __restrict__ omax1, float* __restrict__ osinv1,
                 float* __restrict__ omax2, float* __restrict__ osinv2) {
    int which = blockIdx.y;
    const float* src = which ? att2 : att;
    float* omax  = which ? omax2  : omax1;
    float* osinv = which ? osinv2 : osinv1;

    int r = blockIdx.x;
    const float* p = src + (size_t)r * Ll;
    int tid = threadIdx.x;
    float4 v = ((const float4*)p)[tid];

    float m = fmaxf(fmaxf(v.x, v.y), fmaxf(v.z, v.w));
#pragma unroll
    for (int o = 16; o; o >>= 1) m = fmaxf(m, __shfl_xor_sync(~0u, m, o));
    __shared__ float redm[8], reds[8];
    if ((tid & 31) == 0) redm[tid >> 5] = m;
    __syncthreads();
    float bm = redm[0];
#pragma unroll
    for (int w = 1; w < 8; ++w) bm = fmaxf(bm, redm[w]);

    float s = __expf(v.x - bm) + __expf(v.y - bm) + __expf(v.z - bm) + __expf(v.w - bm);
#pragma unroll
    for (int o = 16; o; o >>= 1) s += __shfl_xor_sync(~0u, s, o);
    if ((tid & 31) == 0) reds[tid >> 5] = s;
    __syncthreads();
    if (tid == 0) {
        float t = 0.f;
#pragma unroll
        for (int w = 0; w < 8; ++w) t += reds[w];
        omax[r]  = bm;
        osinv[r] = 1.f / t;
    }
}

// ---------------------------------------------------------------------------
// Fused normalize + split for both score buffers
// ---------------------------------------------------------------------------
__global__ __launch_bounds__(256)
void k_normsplit2(const float* __restrict__ att,  const float* __restrict__ att2,
                  const float* __restrict__ rmax1, const float* __restrict__ rsinv1,
                  const float* __restrict__ rmax2, const float* __restrict__ rsinv2,
                  __nv_bfloat16* __restrict__ w2hi,  __nv_bfloat16* __restrict__ w2lo,
                  __nv_bfloat16* __restrict__ w1thi, __nv_bfloat16* __restrict__ w1tlo) {
    int which = blockIdx.y;
    const float* src = which ? att2 : att;
    const float* rmax  = which ? rmax2  : rmax1;
    const float* rsinv = which ? rsinv2 : rsinv1;
    __nv_bfloat16* whi = which ? w1thi : w2hi;
    __nv_bfloat16* wlo = which ? w1tlo : w2lo;

    size_t idx4 = (size_t)blockIdx.x * 256 + threadIdx.x;
    size_t base = idx4 * 4;
    int row = (int)(base >> 10);

    float4 a = *(const float4*)&src[base];
    float rm = rmax[row];
    float rs = rsinv[row];
    float w[4];
    w[0] = __expf(a.x - rm) * rs;
    w[1] = __expf(a.y - rm) * rs;
    w[2] = __expf(a.z - rm) * rs;
    w[3] = __expf(a.w - rm) * rs;
    BF4 l4; BF4 h4 = split4(w, l4);
    *(BF4*)&whi[base] = h4;
    *(BF4*)&wlo[base] = l4;
}

// ---------------------------------------------------------------------------
extern "C" void kernel_launch(void* const* d_in, const int* in_sizes, int n_in,
                              void* d_out, int out_size) {
    const float* in1 = (const float*)d_in[0];
    const float* in2 = (const float*)d_in[1];
    float* out = (float*)d_out;

    const int SMEM_BYTES = 81920;   // 2 stages x 40960 (col variant, max)
    cudaFuncSetAttribute(gemmw<true,  true >, cudaFuncAttributeMaxDynamicSharedMemorySize, SMEM_BYTES);
    cudaFuncSetAttribute(gemmw<false, false>, cudaFuncAttributeMaxDynamicSharedMemorySize, SMEM_BYTES);

    float *att, *att2, *rmax1, *rsinv1, *rmax2, *rsinv2;
    __nv_bfloat16 *i1h, *i1l, *i2h, *i2l, *w2h, *w2l, *w1th, *w1tl;
    cudaGetSymbolAddress((void**)&att,  g_att);
    cudaGetSymbolAddress((void**)&att2, g_att2);
    cudaGetSymbolAddress((void**)&i1h,  g_in1hi);
    cudaGetSymbolAddress((void**)&i1l,  g_in1lo);
    cudaGetSymbolAddress((void**)&i2h,  g_in2hi);
    cudaGetSymbolAddress((void**)&i2l,  g_in2lo);
    cudaGetSymbolAddress((void**)&w2h,  g_w2hi);
    cudaGetSymbolAddress((void**)&w2l,  g_w2lo);
    cudaGetSymbolAddress((void**)&w1th, g_w1thi);
    cudaGetSymbolAddress((void**)&w1tl, g_w1tlo);
    cudaGetSymbolAddress((void**)&rmax1,  g_rmax1);
    cudaGetSymbolAddress((void**)&rsinv1, g_rsinv1);
    cudaGetSymbolAddress((void**)&rmax2,  g_rmax2);
    cudaGetSymbolAddress((void**)&rsinv2, g_rsinv2);

    // 1) split both inputs to bf16 hi/lo
    int sblk = (int)(((size_t)Bb * Ll * Dd) / (256 * 4));
    k_split<<<sblk, 256>>>(in1, i1h, i1l);
    k_split<<<sblk, 256>>>(in2, i2h, i2l);

    // 2) scores: att = in1 @ in2^T (K=768); also att2 = att^T
    gemmw<true, true><<<dim3(Ll / 128, Ll / 128, Bb), 256, SMEM_BYTES>>>(
        i1h, i1l, i2h, i2l, Dd, Dd, Dd,
        att, Ll, (size_t)Ll * Dd, (size_t)Ll * Dd, (size_t)Ll * Ll,
        att2, Ll, (size_t)Ll * Ll);

    // 3) fused row stats
    k_rowstats2<<<dim3(Bb * Ll, 2), 256>>>(att, att2, rmax1, rsinv1, rmax2, rsinv2);

    // 4) fused normalize + split
    int nblk = (int)(((size_t)Bb * Ll * Ll) / (256 * 4));
    k_normsplit2<<<dim3(nblk, 2), 256>>>(att, att2, rmax1, rsinv1, rmax2, rsinv2,
                                         w2h, w2l, w1th, w1tl);

    // 5) outA[b,j,d] = sum_i w1t[j,i] * in1[i,d]
    gemmw<false, false><<<dim3(Dd / 128, Ll / 128, Bb), 256, SMEM_BYTES>>>(
        w1th, w1tl, i1h, i1l, Ll, Dd, Ll,
        out, Dd, (size_t)Ll * Ll, (size_t)Ll * Dd, (size_t)Ll * Dd,
        nullptr, 0, 0);

    // 6) outB[b,i,d] = sum_j w2[i,j] * in2[j,d]
    gemmw<false, false><<<dim3(Dd / 128, Ll / 128, Bb), 256, SMEM_BYTES>>>(
        w2h, w2l, i2h, i2l, Ll, Dd, Ll,
        out + (size_t)Bb * Ll * Dd, Dd, (size_t)Ll * Ll, (size_t)Ll * Dd, (size_t)Ll * Dd,
        nullptr, 0, 0);
}

// round 6
// speedup vs baseline: 3.0570x; 1.3853x over previous
#include <cuda_runtime.h>
#include <cuda_fp16.h>
#include <mma.h>
#include <cstdint>
#include <math.h>

using namespace nvcuda;

#define Bb 32
#define Ll 1024
#define Dd 768

// ---------------------------------------------------------------------------
// Scratch (device globals; no allocation allowed)
// ---------------------------------------------------------------------------
__device__ float g_att [(size_t)Bb * Ll * Ll];   // att[i][j]
__device__ float g_att2[(size_t)Bb * Ll * Ll];   // att^T  [j][i]

__device__ __half g_in1hi[(size_t)Bb * Ll * Dd];
__device__ __half g_in1lo[(size_t)Bb * Ll * Dd];
__device__ __half g_in2hi[(size_t)Bb * Ll * Dd];
__device__ __half g_in2lo[(size_t)Bb * Ll * Dd];

__device__ __half g_w2hi [(size_t)Bb * Ll * Ll];   // row-softmax(att)  [i][j]
__device__ __half g_w2lo [(size_t)Bb * Ll * Ll];
__device__ __half g_w1thi[(size_t)Bb * Ll * Ll];   // row-softmax(att2) [j][i]
__device__ __half g_w1tlo[(size_t)Bb * Ll * Ll];

__device__ float g_rmax1 [Bb * Ll];
__device__ float g_rsinv1[Bb * Ll];
__device__ float g_rmax2 [Bb * Ll];
__device__ float g_rsinv2[Bb * Ll];

struct alignas(8) HF4 { __half v[4]; };

__device__ __forceinline__ HF4 split4(const float* vv, HF4& lo) {
    HF4 hi;
#pragma unroll
    for (int k = 0; k < 4; ++k) {
        hi.v[k] = __float2half_rn(vv[k]);
        lo.v[k] = __float2half_rn(vv[k] - __half2float(hi.v[k]));
    }
    return hi;
}

__device__ __forceinline__ uint32_t smem_u32(const void* p) {
    uint32_t a;
    asm("{ .reg .u64 t; cvta.to.shared.u64 t, %1; cvt.u32.u64 %0, t; }"
        : "=r"(a) : "l"(p));
    return a;
}

__device__ __forceinline__ void cp16(uint32_t dst, const void* src) {
    asm volatile("cp.async.cg.shared.global [%0], [%1], 16;" :: "r"(dst), "l"(src));
}
#define CP_COMMIT() asm volatile("cp.async.commit_group;" ::: "memory")
#define CP_WAIT(n)  asm volatile("cp.async.wait_group %0;" :: "n"(n) : "memory")

// ---------------------------------------------------------------------------
// Elementwise split fp32 -> fp16 hi/lo for both inputs (blockIdx.y selects)
// ---------------------------------------------------------------------------
__global__ __launch_bounds__(256)
void k_split2(const float* __restrict__ in1, const float* __restrict__ in2,
              __half* __restrict__ hi1, __half* __restrict__ lo1,
              __half* __restrict__ hi2, __half* __restrict__ lo2) {
    const float* src = blockIdx.y ? in2 : in1;
    __half* hi = blockIdx.y ? hi2 : hi1;
    __half* lo = blockIdx.y ? lo2 : lo1;
    size_t base = ((size_t)blockIdx.x * 256 + threadIdx.x) * 4;
    float4 v = *(const float4*)&src[base];
    float vv[4] = {v.x, v.y, v.z, v.w};
    HF4 l4; HF4 h4 = split4(vv, l4);
    *(HF4*)&hi[base] = h4;
    *(HF4*)&lo[base] = l4;
}

// ---------------------------------------------------------------------------
// Pipelined WMMA fp16 multi-product GEMM, fp32 accum, cp.async double buffer.
//   A: [M,K] row-major, split hi/lo.
//   B_COL=true : B [N,K] col_major frags (hi/lo, NPROD=3: hh + lh + hl)
//   B_COL=false: B [K,N] row_major frags (hi only, NPROD=2: hh + lh)
// CTA 128x128, K-chunk 32, 2 stages. 8 warps = 4(M) x 2(N), warp tile 32x64.
// ---------------------------------------------------------------------------
#define KC 32
#define AP 40            // A/Bcol smem pitch in halves (80B rows, ldmatrix conflict-free)
#define BP 136           // Brow smem pitch in halves (272B rows)
#define A_TILE_B (128 * AP * 2)          // 10240 bytes
#define BROW_TILE_B (KC * BP * 2)        // 8704 bytes
#define STAGE_COL (4 * A_TILE_B)         // 40960
#define STAGE_ROW2 (2 * A_TILE_B + BROW_TILE_B)  // 29184

template <bool B_COL, bool WRITE_T, int NPROD>
__global__ __launch_bounds__(256, 2)
void gemmw(const __half* __restrict__ Ahi, const __half* __restrict__ Alo,
           const __half* __restrict__ Bhi, const __half* __restrict__ Blo,
           int lda, int ldb, int K,
           float* __restrict__ C, int ldc,
           size_t sA, size_t sB, size_t sC,
           float* __restrict__ CT, int ldct, size_t sCT) {
    extern __shared__ char sm[];
    const uint32_t sbase = smem_u32(sm);
    const int STAGE = B_COL ? STAGE_COL : STAGE_ROW2;

    int tid = threadIdx.x;
    int wid = tid >> 5;
    int wm  = wid & 3;
    int wn  = wid >> 2;
    int b   = blockIdx.z;
    int m0  = blockIdx.y * 128;
    int n0  = blockIdx.x * 128;

    const __half* Ah = Ahi + (size_t)b * sA + (size_t)m0 * lda;
    const __half* Al = Alo + (size_t)b * sA + (size_t)m0 * lda;
    const __half* Bh;
    const __half* Bl = nullptr;
    if (B_COL) { Bh = Bhi + (size_t)b * sB + (size_t)n0 * ldb;
                 Bl = Blo + (size_t)b * sB + (size_t)n0 * ldb; }
    else       { Bh = Bhi + (size_t)b * sB + n0; }

    // per-thread load coordinates
    int arow = tid >> 2;            // 0..63 (x2 halves -> 128 rows), KC cols
    int ac16 = (tid & 3) * 8;       // 0..24 halves (covers 32 = KC)
    int brow = tid >> 4;            // 0..15 (x2 halves -> 32 rows = KC)
    int bc16 = (tid & 15) * 8;      // 0..120 halves (covers 128 cols)

    auto load_stage = [&](int st, int k0) {
        uint32_t s = sbase + st * STAGE;
#pragma unroll
        for (int h = 0; h < 2; ++h) {
            int r = arow + h * 64;
            uint32_t d = s + r * (AP * 2) + ac16 * 2;
            cp16(d,            Ah + (size_t)r * lda + k0 + ac16);
            cp16(d + A_TILE_B, Al + (size_t)r * lda + k0 + ac16);
        }
        if (B_COL) {
#pragma unroll
            for (int h = 0; h < 2; ++h) {
                int r = arow + h * 64;
                uint32_t d = s + 2 * A_TILE_B + r * (AP * 2) + ac16 * 2;
                cp16(d,            Bh + (size_t)r * ldb + k0 + ac16);
                if (NPROD == 3)
                    cp16(d + A_TILE_B, Bl + (size_t)r * ldb + k0 + ac16);
            }
        } else {
#pragma unroll
            for (int h = 0; h < 2; ++h) {
                int r = brow + h * 16;
                uint32_t d = s + 2 * A_TILE_B + r * (BP * 2) + bc16 * 2;
                cp16(d, Bh + (size_t)(k0 + r) * ldb + bc16);
            }
        }
    };

    wmma::fragment<wmma::accumulator, 16, 16, 16, float> acc[2][4];
#pragma unroll
    for (int i = 0; i < 2; ++i)
#pragma unroll
        for (int j = 0; j < 4; ++j)
            wmma::fill_fragment(acc[i][j], 0.0f);

    const int NK = K / KC;
    load_stage(0, 0);
    CP_COMMIT();

    for (int it = 0; it < NK; ++it) {
        if (it + 1 < NK) {
            load_stage((it + 1) & 1, (it + 1) * KC);
            CP_COMMIT();
            CP_WAIT(1);
        } else {
            CP_WAIT(0);
        }
        __syncthreads();

        const __half* sAhi = (const __half*)(sm + (it & 1) * STAGE);
        const __half* sAlo = sAhi + A_TILE_B / 2;   // +A_TILE_B bytes
        const __half* sBhi = sAhi + A_TILE_B;       // +2*A_TILE_B bytes
        const __half* sBlo = sBhi + A_TILE_B / 2;   // col variant only

#pragma unroll
        for (int ks = 0; ks < KC / 16; ++ks) {
            wmma::fragment<wmma::matrix_a, 16, 16, 16, __half, wmma::row_major> ah[2], al[2];
#pragma unroll
            for (int fi = 0; fi < 2; ++fi) {
                int ro = (wm * 32 + fi * 16) * AP + ks * 16;
                wmma::load_matrix_sync(ah[fi], &sAhi[ro], AP);
                wmma::load_matrix_sync(al[fi], &sAlo[ro], AP);
            }
            if (B_COL) {
#pragma unroll
                for (int fj = 0; fj < 4; ++fj) {
                    wmma::fragment<wmma::matrix_b, 16, 16, 16, __half, wmma::col_major> bh, bl;
                    int ro = (wn * 64 + fj * 16) * AP + ks * 16;
                    wmma::load_matrix_sync(bh, &sBhi[ro], AP);
                    if (NPROD == 3) wmma::load_matrix_sync(bl, &sBlo[ro], AP);
#pragma unroll
                    for (int fi = 0; fi < 2; ++fi) {
                        wmma::mma_sync(acc[fi][fj], ah[fi], bh, acc[fi][fj]);
                        wmma::mma_sync(acc[fi][fj], al[fi], bh, acc[fi][fj]);
                        if (NPROD == 3)
                            wmma::mma_sync(acc[fi][fj], ah[fi], bl, acc[fi][fj]);
                    }
                }
            } else {
#pragma unroll
                for (int fj = 0; fj < 4; ++fj) {
                    wmma::fragment<wmma::matrix_b, 16, 16, 16, __half, wmma::row_major> bh;
                    int ro = (ks * 16) * BP + wn * 64 + fj * 16;
                    wmma::load_matrix_sync(bh, &sBhi[ro], BP);
#pragma unroll
                    for (int fi = 0; fi < 2; ++fi) {
                        wmma::mma_sync(acc[fi][fj], ah[fi], bh, acc[fi][fj]);
                        wmma::mma_sync(acc[fi][fj], al[fi], bh, acc[fi][fj]);
                    }
                }
            }
        }
        __syncthreads();
    }

    // --- Epilogue ---
    float* Cb = C + (size_t)b * sC;
#pragma unroll
    for (int fi = 0; fi < 2; ++fi)
#pragma unroll
        for (int fj = 0; fj < 4; ++fj) {
            int gr = m0 + wm * 32 + fi * 16;
            int gc = n0 + wn * 64 + fj * 16;
            wmma::store_matrix_sync(&Cb[(size_t)gr * ldc + gc], acc[fi][fj], ldc,
                                    wmma::mem_row_major);
        }

    if (WRITE_T) {
        float* Sf = (float*)sm;    // 128 x 132 fp32 staging = 67584B <= 81920B
#pragma unroll
        for (int fi = 0; fi < 2; ++fi)
#pragma unroll
            for (int fj = 0; fj < 4; ++fj) {
                int lr = wm * 32 + fi * 16;
                int lc = wn * 64 + fj * 16;
                wmma::store_matrix_sync(&Sf[lr * 132 + lc], acc[fi][fj], 132,
                                        wmma::mem_row_major);
            }
        __syncthreads();
        float* CTb = CT + (size_t)b * sCT;
#pragma unroll 4
        for (int it = 0; it < 64; ++it) {
            int q  = tid + it * 256;
            int ii = q & 127;
            int jj = q >> 7;
            CTb[(size_t)(n0 + jj) * ldct + m0 + ii] = Sf[ii * 132 + jj];
        }
    }
}

// ---------------------------------------------------------------------------
// Fused row stats for att and att2 (blockIdx.y selects source)
// ---------------------------------------------------------------------------
__global__ __launch_bounds__(256)
void k_rowstats2(const float* __restrict__ att, const float* __restrict__ att2,
                 float* __restrict__ omax1, float* __restrict__ osinv1,
                 float* __restrict__ omax2, float* __restrict__ osinv2) {
    int which = blockIdx.y;
    const float* src = which ? att2 : att;
    float* omax  = which ? omax2  : omax1;
    float* osinv = which ? osinv2 : osinv1;

    int r = blockIdx.x;
    const float* p = src + (size_t)r * Ll;
    int tid = threadIdx.x;
    float4 v = ((const float4*)p)[tid];

    float m = fmaxf(fmaxf(v.x, v.y), fmaxf(v.z, v.w));
#pragma unroll
    for (int o = 16; o; o >>= 1) m = fmaxf(m, __shfl_xor_sync(~0u, m, o));
    __shared__ float redm[8], reds[8];
    if ((tid & 31) == 0) redm[tid >> 5] = m;
    __syncthreads();
    float bm = redm[0];
#pragma unroll
    for (int w = 1; w < 8; ++w) bm = fmaxf(bm, redm[w]);

    float s = __expf(v.x - bm) + __expf(v.y - bm) + __expf(v.z - bm) + __expf(v.w - bm);
#pragma unroll
    for (int o = 16; o; o >>= 1) s += __shfl_xor_sync(~0u, s, o);
    if ((tid & 31) == 0) reds[tid >> 5] = s;
    __syncthreads();
    if (tid == 0) {
        float t = 0.f;
#pragma unroll
        for (int w = 0; w < 8; ++w) t += reds[w];
        omax[r]  = bm;
        osinv[r] = 1.f / t;
    }
}

// ---------------------------------------------------------------------------
// Fused normalize + split to fp16 hi/lo for both score buffers
// ---------------------------------------------------------------------------
__global__ __launch_bounds__(256)
void k_normsplit2(const float* __restrict__ att,  const float* __restrict__ att2,
                  const float* __restrict__ rmax1, const float* __restrict__ rsinv1,
                  const float* __restrict__ rmax2, const float* __restrict__ rsinv2,
                  __half* __restrict__ w2hi,  __half* __restrict__ w2lo,
                  __half* __restrict__ w1thi, __half* __restrict__ w1tlo) {
    int which = blockIdx.y;
    const float* src = which ? att2 : att;
    const float* rmax  = which ? rmax2  : rmax1;
    const float* rsinv = which ? rsinv2 : rsinv1;
    __half* whi = which ? w1thi : w2hi;
    __half* wlo = which ? w1tlo : w2lo;

    size_t base = ((size_t)blockIdx.x * 256 + threadIdx.x) * 4;
    int row = (int)(base >> 10);

    float4 a = *(const float4*)&src[base];
    float rm = rmax[row];
    float rs = rsinv[row];
    float w[4];
    w[0] = __expf(a.x - rm) * rs;
    w[1] = __expf(a.y - rm) * rs;
    w[2] = __expf(a.z - rm) * rs;
    w[3] = __expf(a.w - rm) * rs;
    HF4 l4; HF4 h4 = split4(w, l4);
    *(HF4*)&whi[base] = h4;
    *(HF4*)&wlo[base] = l4;
}

// ---------------------------------------------------------------------------
extern "C" void kernel_launch(void* const* d_in, const int* in_sizes, int n_in,
                              void* d_out, int out_size) {
    const float* in1 = (const float*)d_in[0];
    const float* in2 = (const float*)d_in[1];
    float* out = (float*)d_out;

    const int SMEM_BYTES = 81920;   // scores variant: 2 stages x 40960
    cudaFuncSetAttribute(gemmw<true,  true,  3>, cudaFuncAttributeMaxDynamicSharedMemorySize, SMEM_BYTES);
    cudaFuncSetAttribute(gemmw<false, false, 2>, cudaFuncAttributeMaxDynamicSharedMemorySize, SMEM_BYTES);

    float *att, *att2, *rmax1, *rsinv1, *rmax2, *rsinv2;
    __half *i1h, *i1l, *i2h, *i2l, *w2h, *w2l, *w1th, *w1tl;
    cudaGetSymbolAddress((void**)&att,  g_att);
    cudaGetSymbolAddress((void**)&att2, g_att2);
    cudaGetSymbolAddress((void**)&i1h,  g_in1hi);
    cudaGetSymbolAddress((void**)&i1l,  g_in1lo);
    cudaGetSymbolAddress((void**)&i2h,  g_in2hi);
    cudaGetSymbolAddress((void**)&i2l,  g_in2lo);
    cudaGetSymbolAddress((void**)&w2h,  g_w2hi);
    cudaGetSymbolAddress((void**)&w2l,  g_w2lo);
    cudaGetSymbolAddress((void**)&w1th, g_w1thi);
    cudaGetSymbolAddress((void**)&w1tl, g_w1tlo);
    cudaGetSymbolAddress((void**)&rmax1,  g_rmax1);
    cudaGetSymbolAddress((void**)&rsinv1, g_rsinv1);
    cudaGetSymbolAddress((void**)&rmax2,  g_rmax2);
    cudaGetSymbolAddress((void**)&rsinv2, g_rsinv2);

    // 1) split both inputs to fp16 hi/lo (fused)
    int sblk = (int)(((size_t)Bb * Ll * Dd) / (256 * 4));
    k_split2<<<dim3(sblk, 2), 256>>>(in1, in2, i1h, i1l, i2h, i2l);

    // 2) scores: att = in1 @ in2^T (K=768, 3 products); also att2 = att^T
    gemmw<true, true, 3><<<dim3(Ll / 128, Ll / 128, Bb), 256, SMEM_BYTES>>>(
        i1h, i1l, i2h, i2l, Dd, Dd, Dd,
        att, Ll, (size_t)Ll * Dd, (size_t)Ll * Dd, (size_t)Ll * Ll,
        att2, Ll, (size_t)Ll * Ll);

    // 3) fused row stats
    k_rowstats2<<<dim3(Bb * Ll, 2), 256>>>(att, att2, rmax1, rsinv1, rmax2, rsinv2);

    // 4) fused normalize + split (fp16 hi/lo: w exact to 2^-22)
    int nblk = (int)(((size_t)Bb * Ll * Ll) / (256 * 4));
    k_normsplit2<<<dim3(nblk, 2), 256>>>(att, att2, rmax1, rsinv1, rmax2, rsinv2,
                                         w2h, w2l, w1th, w1tl);

    // 5) outA[b,j,d] = sum_i w1t[j,i] * in1[i,d]   (2 products: w exact, B=fp16(in1))
    gemmw<false, false, 2><<<dim3(Dd / 128, Ll / 128, Bb), 256, SMEM_BYTES>>>(
        w1th, w1tl, i1h, nullptr, Ll, Dd, Ll,
        out, Dd, (size_t)Ll * Ll, (size_t)Ll * Dd, (size_t)Ll * Dd,
        nullptr, 0, 0);

    // 6) outB[b,i,d] = sum_j w2[i,j] * in2[j,d]    (2 products)
    gemmw<false, false, 2><<<dim3(Dd / 128, Ll / 128, Bb), 256, SMEM_BYTES>>>(
        w2h, w2l, i2h, nullptr, Ll, Dd, Ll,
        out + (size_t)Bb * Ll * Dd, Dd, (size_t)Ll * Ll, (size_t)Ll * Dd, (size_t)Ll * Dd,
        nullptr, 0, 0);
}

// round 7
// speedup vs baseline: 3.3995x; 1.1120x over previous
#include <cuda_runtime.h>
#include <cuda_fp16.h>
#include <mma.h>
#include <cstdint>
#include <math.h>

using namespace nvcuda;

#define Bb 32
#define Ll 1024
#define Dd 768
#define SHIFT 120.0f

// ---------------------------------------------------------------------------
// Scratch (device globals; no allocation allowed)
// ---------------------------------------------------------------------------
__device__ float g_eatt[(size_t)Bb * Ll * Ll];   // exp(att - SHIFT)  [i][j]

__device__ __half g_in1hi[(size_t)Bb * Ll * Dd];
__device__ __half g_in1lo[(size_t)Bb * Ll * Dd];
__device__ __half g_in2hi[(size_t)Bb * Ll * Dd];
__device__ __half g_in2lo[(size_t)Bb * Ll * Dd];

__device__ __half g_w2hi[(size_t)Bb * Ll * Ll];   // axis-2 softmax  [i][j]
__device__ __half g_w2lo[(size_t)Bb * Ll * Ll];
__device__ __half g_w1hi[(size_t)Bb * Ll * Ll];   // axis-1 softmax  [i][j]
__device__ __half g_w1lo[(size_t)Bb * Ll * Ll];

__device__ float g_rsum[Bb * Ll];   // per-row sums -> inverted in place
__device__ float g_csum[Bb * Ll];   // per-col sums -> inverted in place

struct alignas(8) HF4 { __half v[4]; };

__device__ __forceinline__ HF4 split4(const float* vv, HF4& lo) {
    HF4 hi;
#pragma unroll
    for (int k = 0; k < 4; ++k) {
        hi.v[k] = __float2half_rn(vv[k]);
        lo.v[k] = __float2half_rn(vv[k] - __half2float(hi.v[k]));
    }
    return hi;
}

__device__ __forceinline__ uint32_t smem_u32(const void* p) {
    uint32_t a;
    asm("{ .reg .u64 t; cvta.to.shared.u64 t, %1; cvt.u32.u64 %0, t; }"
        : "=r"(a) : "l"(p));
    return a;
}

__device__ __forceinline__ void cp16(uint32_t dst, const void* src) {
    asm volatile("cp.async.cg.shared.global [%0], [%1], 16;" :: "r"(dst), "l"(src));
}
#define CP_COMMIT() asm volatile("cp.async.commit_group;" ::: "memory")
#define CP_WAIT(n)  asm volatile("cp.async.wait_group %0;" :: "n"(n) : "memory")

// ---------------------------------------------------------------------------
// Elementwise split fp32 -> fp16 hi/lo for both inputs
// ---------------------------------------------------------------------------
__global__ __launch_bounds__(256)
void k_split2(const float* __restrict__ in1, const float* __restrict__ in2,
              __half* __restrict__ hi1, __half* __restrict__ lo1,
              __half* __restrict__ hi2, __half* __restrict__ lo2) {
    const float* src = blockIdx.y ? in2 : in1;
    __half* hi = blockIdx.y ? hi2 : hi1;
    __half* lo = blockIdx.y ? lo2 : lo1;
    size_t base = ((size_t)blockIdx.x * 256 + threadIdx.x) * 4;
    float4 v = *(const float4*)&src[base];
    float vv[4] = {v.x, v.y, v.z, v.w};
    HF4 l4; HF4 h4 = split4(vv, l4);
    *(HF4*)&hi[base] = h4;
    *(HF4*)&lo[base] = l4;
}

// ---------------------------------------------------------------------------
// Pipelined WMMA fp16 multi-product GEMM. CTA 128x128, KC=32, 2-stage cp.async.
//   A: split hi/lo. A_COL: A stored [K,M] (col_major frags) else [M,K].
//   B_COL: B stored [N,K] col_major frags (hi/lo, 3 products) else [K,N] (hi, 2).
//   REDUCE: epilogue computes e=exp(v-SHIFT), row/col partial sums (atomicAdd),
//           and writes e (not v) to C.
// ---------------------------------------------------------------------------
#define KC 32
#define AP 40            // [M,K]-tile pitch in halves (80B rows)
#define BP 136           // [K,N]/[K,M]-tile pitch in halves (272B rows)
#define TILE_MK (128 * AP * 2)   // 10240 bytes: 128 rows x KC halves
#define TILE_KN (KC * BP * 2)    // 8704  bytes: KC rows x 128 halves

template <bool A_COL, bool B_COL, bool REDUCE, int NPROD>
__global__ __launch_bounds__(256, 2)
void gemmw(const __half* __restrict__ Ahi, const __half* __restrict__ Alo,
           const __half* __restrict__ Bhi, const __half* __restrict__ Blo,
           int lda, int ldb, int K,
           float* __restrict__ C, int ldc,
           size_t sA, size_t sB, size_t sC,
           float* __restrict__ rsum, float* __restrict__ csum) {
    extern __shared__ char sm[];
    const uint32_t sbase = smem_u32(sm);
    constexpr int ATILE = A_COL ? TILE_KN : TILE_MK;
    constexpr int BTILE = B_COL ? TILE_MK : TILE_KN;
    constexpr int STAGE = 2 * ATILE + (NPROD == 3 ? 2 : 1) * BTILE;

    int tid = threadIdx.x;
    int wid = tid >> 5;
    int wm  = wid & 3;
    int wn  = wid >> 2;
    int b   = blockIdx.z;
    int m0  = blockIdx.y * 128;
    int n0  = blockIdx.x * 128;

    const __half* Ah = Ahi + (size_t)b * sA + (A_COL ? (size_t)m0 : (size_t)m0 * lda);
    const __half* Al = Alo + (size_t)b * sA + (A_COL ? (size_t)m0 : (size_t)m0 * lda);
    const __half* Bh = Bhi + (size_t)b * sB + (B_COL ? (size_t)n0 * ldb : (size_t)n0);
    const __half* Bl = B_COL ? (Blo + (size_t)b * sB + (size_t)n0 * ldb) : nullptr;

    // load coordinates
    int arow = tid >> 2;            // [M,K] tiles: 0..63 (x2 -> 128 rows)
    int ac16 = (tid & 3) * 8;       // covers KC=32 halves
    int brow = tid >> 4;            // [K,*] tiles: 0..15 (x2 -> 32 rows)
    int bc16 = (tid & 15) * 8;      // covers 128 halves

    auto load_stage = [&](int st, int k0) {
        uint32_t s = sbase + st * STAGE;
        if (!A_COL) {
#pragma unroll
            for (int h = 0; h < 2; ++h) {
                int r = arow + h * 64;
                uint32_t d = s + r * (AP * 2) + ac16 * 2;
                cp16(d,         Ah + (size_t)r * lda + k0 + ac16);
                cp16(d + ATILE, Al + (size_t)r * lda + k0 + ac16);
            }
        } else {
#pragma unroll
            for (int h = 0; h < 2; ++h) {
                int r = brow + h * 16;
                uint32_t d = s + r * (BP * 2) + bc16 * 2;
                cp16(d,         Ah + (size_t)(k0 + r) * lda + bc16);
                cp16(d + ATILE, Al + (size_t)(k0 + r) * lda + bc16);
            }
        }
        if (B_COL) {
#pragma unroll
            for (int h = 0; h < 2; ++h) {
                int r = arow + h * 64;
                uint32_t d = s + 2 * ATILE + r * (AP * 2) + ac16 * 2;
                cp16(d, Bh + (size_t)r * ldb + k0 + ac16);
                if (NPROD == 3)
                    cp16(d + BTILE, Bl + (size_t)r * ldb + k0 + ac16);
            }
        } else {
#pragma unroll
            for (int h = 0; h < 2; ++h) {
                int r = brow + h * 16;
                uint32_t d = s + 2 * ATILE + r * (BP * 2) + bc16 * 2;
                cp16(d, Bh + (size_t)(k0 + r) * ldb + bc16);
            }
        }
    };

    wmma::fragment<wmma::accumulator, 16, 16, 16, float> acc[2][4];
#pragma unroll
    for (int i = 0; i < 2; ++i)
#pragma unroll
        for (int j = 0; j < 4; ++j)
            wmma::fill_fragment(acc[i][j], 0.0f);

    const int NK = K / KC;
    load_stage(0, 0);
    CP_COMMIT();

    for (int it = 0; it < NK; ++it) {
        if (it + 1 < NK) {
            load_stage((it + 1) & 1, (it + 1) * KC);
            CP_COMMIT();
            CP_WAIT(1);
        } else {
            CP_WAIT(0);
        }
        __syncthreads();

        const __half* sA0 = (const __half*)(sm + (it & 1) * STAGE);
        const __half* sAl = sA0 + ATILE / 2;
        const __half* sB0 = (const __half*)((const char*)sA0 + 2 * ATILE);
        const __half* sBl = sB0 + BTILE / 2;

#pragma unroll
        for (int ks = 0; ks < KC / 16; ++ks) {
            if constexpr (B_COL) {
                // scores: A row-major, B col-major, 3 products
                wmma::fragment<wmma::matrix_a, 16, 16, 16, __half, wmma::row_major> ah[2], al[2];
#pragma unroll
                for (int fi = 0; fi < 2; ++fi) {
                    int ro = (wm * 32 + fi * 16) * AP + ks * 16;
                    wmma::load_matrix_sync(ah[fi], &sA0[ro], AP);
                    wmma::load_matrix_sync(al[fi], &sAl[ro], AP);
                }
#pragma unroll
                for (int fj = 0; fj < 4; ++fj) {
                    wmma::fragment<wmma::matrix_b, 16, 16, 16, __half, wmma::col_major> bh, bl;
                    int ro = (wn * 64 + fj * 16) * AP + ks * 16;
                    wmma::load_matrix_sync(bh, &sB0[ro], AP);
                    wmma::load_matrix_sync(bl, &sBl[ro], AP);
#pragma unroll
                    for (int fi = 0; fi < 2; ++fi) {
                        wmma::mma_sync(acc[fi][fj], ah[fi], bh, acc[fi][fj]);
                        wmma::mma_sync(acc[fi][fj], al[fi], bh, acc[fi][fj]);
                        wmma::mma_sync(acc[fi][fj], ah[fi], bl, acc[fi][fj]);
                    }
                }
            } else if constexpr (A_COL) {
                // outA: A col-major [K,M], B row-major [K,N], 2 products
                wmma::fragment<wmma::matrix_a, 16, 16, 16, __half, wmma::col_major> ah[2], al[2];
#pragma unroll
                for (int fi = 0; fi < 2; ++fi) {
                    int ro = (ks * 16) * BP + wm * 32 + fi * 16;
                    wmma::load_matrix_sync(ah[fi], &sA0[ro], BP);
                    wmma::load_matrix_sync(al[fi], &sAl[ro], BP);
                }
#pragma unroll
                for (int fj = 0; fj < 4; ++fj) {
                    wmma::fragment<wmma::matrix_b, 16, 16, 16, __half, wmma::row_major> bh;
                    int ro = (ks * 16) * BP + wn * 64 + fj * 16;
                    wmma::load_matrix_sync(bh, &sB0[ro], BP);
#pragma unroll
                    for (int fi = 0; fi < 2; ++fi) {
                        wmma::mma_sync(acc[fi][fj], ah[fi], bh, acc[fi][fj]);
                        wmma::mma_sync(acc[fi][fj], al[fi], bh, acc[fi][fj]);
                    }
                }
            } else {
                // outB: A row-major, B row-major, 2 products
                wmma::fragment<wmma::matrix_a, 16, 16, 16, __half, wmma::row_major> ah[2], al[2];
#pragma unroll
                for (int fi = 0; fi < 2; ++fi) {
                    int ro = (wm * 32 + fi * 16) * AP + ks * 16;
                    wmma::load_matrix_sync(ah[fi], &sA0[ro], AP);
                    wmma::load_matrix_sync(al[fi], &sAl[ro], AP);
                }
#pragma unroll
                for (int fj = 0; fj < 4; ++fj) {
                    wmma::fragment<wmma::matrix_b, 16, 16, 16, __half, wmma::row_major> bh;
                    int ro = (ks * 16) * BP + wn * 64 + fj * 16;
                    wmma::load_matrix_sync(bh, &sB0[ro], BP);
#pragma unroll
                    for (int fi = 0; fi < 2; ++fi) {
                        wmma::mma_sync(acc[fi][fj], ah[fi], bh, acc[fi][fj]);
                        wmma::mma_sync(acc[fi][fj], al[fi], bh, acc[fi][fj]);
                    }
                }
            }
        }
        __syncthreads();
    }

    // --- Epilogue ---
    float* Cb = C + (size_t)b * sC;
    if constexpr (!REDUCE) {
#pragma unroll
        for (int fi = 0; fi < 2; ++fi)
#pragma unroll
            for (int fj = 0; fj < 4; ++fj) {
                int gr = m0 + wm * 32 + fi * 16;
                int gc = n0 + wn * 64 + fj * 16;
                wmma::store_matrix_sync(&Cb[(size_t)gr * ldc + gc], acc[fi][fj], ldc,
                                        wmma::mem_row_major);
            }
    } else {
        // stage tile in smem; exp + row/col partial sums + coalesced e write
        float* Sf = (float*)sm;   // 128 x 132 fp32 = 67584 B (smem is free now)
#pragma unroll
        for (int fi = 0; fi < 2; ++fi)
#pragma unroll
            for (int fj = 0; fj < 4; ++fj) {
                int lr = wm * 32 + fi * 16;
                int lc = wn * 64 + fj * 16;
                wmma::store_matrix_sync(&Sf[lr * 132 + lc], acc[fi][fj], 132,
                                        wmma::mem_row_major);
            }
        __syncthreads();

        // row pass: exp in place + row sums
        {
            int r = tid >> 1, half = tid & 1;
            float* row = Sf + r * 132 + half * 64;
            float s = 0.f;
#pragma unroll 8
            for (int c = 0; c < 64; ++c) {
                float e = __expf(row[c] - SHIFT);
                row[c] = e;
                s += e;
            }
            s += __shfl_xor_sync(0xffffffffu, s, 1);
            if (!half) atomicAdd(&rsum[(size_t)b * Ll + m0 + r], s);
        }
        __syncthreads();

        // col pass: col sums over exp'd tile
        {
            int c = tid >> 1, half = tid & 1;
            float s = 0.f;
#pragma unroll 8
            for (int r = 0; r < 64; ++r)
                s += Sf[(half * 64 + r) * 132 + c];
            s += __shfl_xor_sync(0xffffffffu, s, 1);
            if (!half) atomicAdd(&csum[(size_t)b * Ll + n0 + c], s);
        }
        __syncthreads();

        // coalesced write of e tile
#pragma unroll 4
        for (int it2 = 0; it2 < 16; ++it2) {
            int q  = tid + it2 * 256;      // float4 index in 128x128 tile
            int ii = q >> 5;
            int c4 = (q & 31) * 4;
            float4 v = *(float4*)&Sf[ii * 132 + c4];
            *(float4*)&Cb[(size_t)(m0 + ii) * ldc + n0 + c4] = v;
        }
    }
}

// ---------------------------------------------------------------------------
// Invert sums in place (rsum/csum -> reciprocals)
// ---------------------------------------------------------------------------
__global__ __launch_bounds__(256)
void k_invert(float* __restrict__ rsum, float* __restrict__ csum) {
    int i = blockIdx.x * 256 + threadIdx.x;
    float* p = (i < Bb * Ll) ? (rsum + i) : (csum + i - Bb * Ll);
    *p = 1.0f / *p;
}

// ---------------------------------------------------------------------------
// Normalize + split: w2 = e * rsinv[i], w1 = e * csinv[j]  (single e read)
// ---------------------------------------------------------------------------
__global__ __launch_bounds__(256)
void k_norm(const float* __restrict__ eatt,
            const float* __restrict__ rsinv, const float* __restrict__ csinv,
            __half* __restrict__ w2hi, __half* __restrict__ w2lo,
            __half* __restrict__ w1hi, __half* __restrict__ w1lo) {
    size_t base = ((size_t)blockIdx.x * 256 + threadIdx.x) * 4;
    int bi = (int)(base >> 10);            // b*Ll + i
    int j  = (int)(base & (Ll - 1));
    int b  = bi >> 10;

    float4 e  = *(const float4*)&eatt[base];
    float  rs = rsinv[bi];
    float4 cs = *(const float4*)&csinv[(size_t)b * Ll + j];

    float w2[4] = {e.x * rs, e.y * rs, e.z * rs, e.w * rs};
    float w1[4] = {e.x * cs.x, e.y * cs.y, e.z * cs.z, e.w * cs.w};

    HF4 l2; HF4 h2 = split4(w2, l2);
    HF4 l1; HF4 h1 = split4(w1, l1);
    *(HF4*)&w2hi[base] = h2;
    *(HF4*)&w2lo[base] = l2;
    *(HF4*)&w1hi[base] = h1;
    *(HF4*)&w1lo[base] = l1;
}

// ---------------------------------------------------------------------------
extern "C" void kernel_launch(void* const* d_in, const int* in_sizes, int n_in,
                              void* d_out, int out_size) {
    const float* in1 = (const float*)d_in[0];
    const float* in2 = (const float*)d_in[1];
    float* out = (float*)d_out;

    // smem per variant (2 stages; scores also needs 67584B epilogue staging)
    const int SMEM_SCORES = 81920;            // 2 x 40960
    const int SMEM_OUTA   = 2 * (2 * TILE_KN + TILE_KN);   // 52224
    const int SMEM_OUTB   = 2 * (2 * TILE_MK + TILE_KN);   // 58368
    cudaFuncSetAttribute(gemmw<false, true,  true,  3>, cudaFuncAttributeMaxDynamicSharedMemorySize, SMEM_SCORES);
    cudaFuncSetAttribute(gemmw<true,  false, false, 2>, cudaFuncAttributeMaxDynamicSharedMemorySize, SMEM_OUTA);
    cudaFuncSetAttribute(gemmw<false, false, false, 2>, cudaFuncAttributeMaxDynamicSharedMemorySize, SMEM_OUTB);

    float *eatt, *rsum, *csum;
    __half *i1h, *i1l, *i2h, *i2l, *w2h, *w2l, *w1h, *w1l;
    cudaGetSymbolAddress((void**)&eatt, g_eatt);
    cudaGetSymbolAddress((void**)&rsum, g_rsum);
    cudaGetSymbolAddress((void**)&csum, g_csum);
    cudaGetSymbolAddress((void**)&i1h,  g_in1hi);
    cudaGetSymbolAddress((void**)&i1l,  g_in1lo);
    cudaGetSymbolAddress((void**)&i2h,  g_in2hi);
    cudaGetSymbolAddress((void**)&i2l,  g_in2lo);
    cudaGetSymbolAddress((void**)&w2h,  g_w2hi);
    cudaGetSymbolAddress((void**)&w2l,  g_w2lo);
    cudaGetSymbolAddress((void**)&w1h,  g_w1hi);
    cudaGetSymbolAddress((void**)&w1l,  g_w1lo);

    // 0) zero the sum accumulators
    cudaMemsetAsync(rsum, 0, Bb * Ll * sizeof(float));
    cudaMemsetAsync(csum, 0, Bb * Ll * sizeof(float));

    // 1) split inputs to fp16 hi/lo
    int sblk = (int)(((size_t)Bb * Ll * Dd) / (256 * 4));
    k_split2<<<dim3(sblk, 2), 256>>>(in1, in2, i1h, i1l, i2h, i2l);

    // 2) scores GEMM (3 products) + fused exp/row-sum/col-sum epilogue -> eatt
    gemmw<false, true, true, 3><<<dim3(Ll / 128, Ll / 128, Bb), 256, SMEM_SCORES>>>(
        i1h, i1l, i2h, i2l, Dd, Dd, Dd,
        eatt, Ll, (size_t)Ll * Dd, (size_t)Ll * Dd, (size_t)Ll * Ll,
        rsum, csum);

    // 3) invert sums
    k_invert<<<(2 * Bb * Ll) / 256, 256>>>(rsum, csum);

    // 4) scale + split to fp16 hi/lo (both weight matrices, one eatt read)
    int nblk = (int)(((size_t)Bb * Ll * Ll) / (256 * 4));
    k_norm<<<nblk, 256>>>(eatt, rsum, csum, w2h, w2l, w1h, w1l);

    // 5) outA[b,j,d] = sum_i w1[i,j] * in1[i,d]  (A = w1 col-major, 2 products)
    gemmw<true, false, false, 2><<<dim3(Dd / 128, Ll / 128, Bb), 256, SMEM_OUTA>>>(
        w1h, w1l, i1h, nullptr, Ll, Dd, Ll,
        out, Dd, (size_t)Ll * Ll, (size_t)Ll * Dd, (size_t)Ll * Dd,
        nullptr, nullptr);

    // 6) outB[b,i,d] = sum_j w2[i,j] * in2[j,d]  (A = w2 row-major, 2 products)
    gemmw<false, false, false, 2><<<dim3(Dd / 128, Ll / 128, Bb), 256, SMEM_OUTB>>>(
        w2h, w2l, i2h, nullptr, Ll, Dd, Ll,
        out + (size_t)Bb * Ll * Dd, Dd, (size_t)Ll * Ll, (size_t)Ll * Dd, (size_t)Ll * Dd,
        nullptr, nullptr);
}

// round 8
// speedup vs baseline: 4.4670x; 1.3140x over previous
#include <cuda_runtime.h>
#include <cuda_fp16.h>
#include <mma.h>
#include <cstdint>
#include <math.h>

using namespace nvcuda;

#define Bb 32
#define Ll 1024
#define Dd 768
#define SHIFT 120.0f

// ---------------------------------------------------------------------------
// Scratch (device globals; no allocation allowed)
// ---------------------------------------------------------------------------
__device__ float g_eatt[(size_t)Bb * Ll * Ll];   // exp(att - SHIFT)  [i][j]

__device__ __half g_in1hi[(size_t)Bb * Ll * Dd];
__device__ __half g_in1lo[(size_t)Bb * Ll * Dd];
__device__ __half g_in2hi[(size_t)Bb * Ll * Dd];
__device__ __half g_in2lo[(size_t)Bb * Ll * Dd];

__device__ __half g_w2hi[(size_t)Bb * Ll * Ll];   // axis-2 softmax  [i][j]
__device__ __half g_w1hi[(size_t)Bb * Ll * Ll];   // axis-1 softmax  [i][j]

__device__ float g_rsum[Bb * Ll];   // per-row sums -> inverted in place
__device__ float g_csum[Bb * Ll];   // per-col sums -> inverted in place

struct alignas(8) HF4 { __half v[4]; };

__device__ __forceinline__ HF4 split4(const float* vv, HF4& lo) {
    HF4 hi;
#pragma unroll
    for (int k = 0; k < 4; ++k) {
        hi.v[k] = __float2half_rn(vv[k]);
        lo.v[k] = __float2half_rn(vv[k] - __half2float(hi.v[k]));
    }
    return hi;
}

__device__ __forceinline__ uint32_t smem_u32(const void* p) {
    uint32_t a;
    asm("{ .reg .u64 t; cvta.to.shared.u64 t, %1; cvt.u32.u64 %0, t; }"
        : "=r"(a) : "l"(p));
    return a;
}

__device__ __forceinline__ void cp16(uint32_t dst, const void* src) {
    asm volatile("cp.async.cg.shared.global [%0], [%1], 16;" :: "r"(dst), "l"(src));
}
#define CP_COMMIT() asm volatile("cp.async.commit_group;" ::: "memory")
#define CP_WAIT(n)  asm volatile("cp.async.wait_group %0;" :: "n"(n) : "memory")

// ---------------------------------------------------------------------------
// Elementwise split fp32 -> fp16 hi/lo for both inputs
// ---------------------------------------------------------------------------
__global__ __launch_bounds__(256)
void k_split2(const float* __restrict__ in1, const float* __restrict__ in2,
              __half* __restrict__ hi1, __half* __restrict__ lo1,
              __half* __restrict__ hi2, __half* __restrict__ lo2) {
    const float* src = blockIdx.y ? in2 : in1;
    __half* hi = blockIdx.y ? hi2 : hi1;
    __half* lo = blockIdx.y ? lo2 : lo1;
    size_t base = ((size_t)blockIdx.x * 256 + threadIdx.x) * 4;
    float4 v = *(const float4*)&src[base];
    float vv[4] = {v.x, v.y, v.z, v.w};
    HF4 l4; HF4 h4 = split4(vv, l4);
    *(HF4*)&hi[base] = h4;
    *(HF4*)&lo[base] = l4;
}

// ---------------------------------------------------------------------------
// Pipelined WMMA fp16 GEMM. CTA 128x128, KC=32, 2-stage cp.async.
//   NPROD=3: scores (A hi/lo row-major, B hi/lo col-major: hh + lh + hl)
//   NPROD=1: outputs (A hi only [col or row major], B hi only row-major)
//   REDUCE: epilogue computes e=exp(v-SHIFT), row/col sums (atomicAdd), writes e.
// ---------------------------------------------------------------------------
#define KC 32
#define AP 40            // [M,K]-tile pitch in halves (80B rows)
#define BP 136           // [K,N]/[K,M]-tile pitch in halves (272B rows)
#define TILE_MK (128 * AP * 2)   // 10240 bytes: 128 rows x KC halves
#define TILE_KN (KC * BP * 2)    // 8704  bytes: KC rows x 128 halves

template <bool A_COL, bool B_COL, bool REDUCE, int NPROD>
__global__ __launch_bounds__(256, 2)
void gemmw(const __half* __restrict__ Ahi, const __half* __restrict__ Alo,
           const __half* __restrict__ Bhi, const __half* __restrict__ Blo,
           int lda, int ldb, int K,
           float* __restrict__ C, int ldc,
           size_t sA, size_t sB, size_t sC,
           float* __restrict__ rsum, float* __restrict__ csum) {
    extern __shared__ char sm[];
    const uint32_t sbase = smem_u32(sm);
    constexpr int ATILE = A_COL ? TILE_KN : TILE_MK;
    constexpr int BTILE = B_COL ? TILE_MK : TILE_KN;
    constexpr int NA = (NPROD == 3) ? 2 : 1;     // A terms stored
    constexpr int NB = (NPROD == 3) ? 2 : 1;     // B terms stored
    constexpr int STAGE = NA * ATILE + NB * BTILE;

    int tid = threadIdx.x;
    int wid = tid >> 5;
    int wm  = wid & 3;
    int wn  = wid >> 2;
    int b   = blockIdx.z;
    int m0  = blockIdx.y * 128;
    int n0  = blockIdx.x * 128;

    const __half* Ah = Ahi + (size_t)b * sA + (A_COL ? (size_t)m0 : (size_t)m0 * lda);
    const __half* Al = (NPROD == 3) ? (Alo + (size_t)b * sA + (size_t)m0 * lda) : nullptr;
    const __half* Bh = Bhi + (size_t)b * sB + (B_COL ? (size_t)n0 * ldb : (size_t)n0);
    const __half* Bl = (B_COL && NPROD == 3) ? (Blo + (size_t)b * sB + (size_t)n0 * ldb) : nullptr;

    // load coordinates
    int arow = tid >> 2;            // [M,K] tiles: 0..63 (x2 -> 128 rows)
    int ac16 = (tid & 3) * 8;       // covers KC=32 halves
    int brow = tid >> 4;            // [K,*] tiles: 0..15 (x2 -> 32 rows)
    int bc16 = (tid & 15) * 8;      // covers 128 halves

    auto load_stage = [&](int st, int k0) {
        uint32_t s = sbase + st * STAGE;
        if (!A_COL) {
#pragma unroll
            for (int h = 0; h < 2; ++h) {
                int r = arow + h * 64;
                uint32_t d = s + r * (AP * 2) + ac16 * 2;
                cp16(d, Ah + (size_t)r * lda + k0 + ac16);
                if (NPROD == 3)
                    cp16(d + ATILE, Al + (size_t)r * lda + k0 + ac16);
            }
        } else {
#pragma unroll
            for (int h = 0; h < 2; ++h) {
                int r = brow + h * 16;
                uint32_t d = s + r * (BP * 2) + bc16 * 2;
                cp16(d, Ah + (size_t)(k0 + r) * lda + bc16);
            }
        }
        if (B_COL) {
#pragma unroll
            for (int h = 0; h < 2; ++h) {
                int r = arow + h * 64;
                uint32_t d = s + NA * ATILE + r * (AP * 2) + ac16 * 2;
                cp16(d, Bh + (size_t)r * ldb + k0 + ac16);
                if (NPROD == 3)
                    cp16(d + BTILE, Bl + (size_t)r * ldb + k0 + ac16);
            }
        } else {
#pragma unroll
            for (int h = 0; h < 2; ++h) {
                int r = brow + h * 16;
                uint32_t d = s + NA * ATILE + r * (BP * 2) + bc16 * 2;
                cp16(d, Bh + (size_t)(k0 + r) * ldb + bc16);
            }
        }
    };

    wmma::fragment<wmma::accumulator, 16, 16, 16, float> acc[2][4];
#pragma unroll
    for (int i = 0; i < 2; ++i)
#pragma unroll
        for (int j = 0; j < 4; ++j)
            wmma::fill_fragment(acc[i][j], 0.0f);

    const int NK = K / KC;
    load_stage(0, 0);
    CP_COMMIT();

    for (int it = 0; it < NK; ++it) {
        if (it + 1 < NK) {
            load_stage((it + 1) & 1, (it + 1) * KC);
            CP_COMMIT();
            CP_WAIT(1);
        } else {
            CP_WAIT(0);
        }
        __syncthreads();

        const __half* sA0 = (const __half*)(sm + (it & 1) * STAGE);
        const __half* sAl = sA0 + ATILE / 2;
        const __half* sB0 = (const __half*)((const char*)sA0 + NA * ATILE);
        const __half* sBl = sB0 + BTILE / 2;

#pragma unroll
        for (int ks = 0; ks < KC / 16; ++ks) {
            if constexpr (NPROD == 3) {
                // scores: A row-major hi/lo, B col-major hi/lo, 3 products
                wmma::fragment<wmma::matrix_a, 16, 16, 16, __half, wmma::row_major> ah[2], al[2];
#pragma unroll
                for (int fi = 0; fi < 2; ++fi) {
                    int ro = (wm * 32 + fi * 16) * AP + ks * 16;
                    wmma::load_matrix_sync(ah[fi], &sA0[ro], AP);
                    wmma::load_matrix_sync(al[fi], &sAl[ro], AP);
                }
#pragma unroll
                for (int fj = 0; fj < 4; ++fj) {
                    wmma::fragment<wmma::matrix_b, 16, 16, 16, __half, wmma::col_major> bh, bl;
                    int ro = (wn * 64 + fj * 16) * AP + ks * 16;
                    wmma::load_matrix_sync(bh, &sB0[ro], AP);
                    wmma::load_matrix_sync(bl, &sBl[ro], AP);
#pragma unroll
                    for (int fi = 0; fi < 2; ++fi) {
                        wmma::mma_sync(acc[fi][fj], ah[fi], bh, acc[fi][fj]);
                        wmma::mma_sync(acc[fi][fj], al[fi], bh, acc[fi][fj]);
                        wmma::mma_sync(acc[fi][fj], ah[fi], bl, acc[fi][fj]);
                    }
                }
            } else if constexpr (A_COL) {
                // outA: A col-major [K,M] hi, B row-major [K,N] hi, 1 product
                wmma::fragment<wmma::matrix_a, 16, 16, 16, __half, wmma::col_major> ah[2];
#pragma unroll
                for (int fi = 0; fi < 2; ++fi) {
                    int ro = (ks * 16) * BP + wm * 32 + fi * 16;
                    wmma::load_matrix_sync(ah[fi], &sA0[ro], BP);
                }
#pragma unroll
                for (int fj = 0; fj < 4; ++fj) {
                    wmma::fragment<wmma::matrix_b, 16, 16, 16, __half, wmma::row_major> bh;
                    int ro = (ks * 16) * BP + wn * 64 + fj * 16;
                    wmma::load_matrix_sync(bh, &sB0[ro], BP);
#pragma unroll
                    for (int fi = 0; fi < 2; ++fi)
                        wmma::mma_sync(acc[fi][fj], ah[fi], bh, acc[fi][fj]);
                }
            } else {
                // outB: A row-major hi, B row-major hi, 1 product
                wmma::fragment<wmma::matrix_a, 16, 16, 16, __half, wmma::row_major> ah[2];
#pragma unroll
                for (int fi = 0; fi < 2; ++fi) {
                    int ro = (wm * 32 + fi * 16) * AP + ks * 16;
                    wmma::load_matrix_sync(ah[fi], &sA0[ro], AP);
                }
#pragma unroll
                for (int fj = 0; fj < 4; ++fj) {
                    wmma::fragment<wmma::matrix_b, 16, 16, 16, __half, wmma::row_major> bh;
                    int ro = (ks * 16) * BP + wn * 64 + fj * 16;
                    wmma::load_matrix_sync(bh, &sB0[ro], BP);
#pragma unroll
                    for (int fi = 0; fi < 2; ++fi)
                        wmma::mma_sync(acc[fi][fj], ah[fi], bh, acc[fi][fj]);
                }
            }
        }
        __syncthreads();
    }

    // --- Epilogue ---
    float* Cb = C + (size_t)b * sC;
    if constexpr (!REDUCE) {
#pragma unroll
        for (int fi = 0; fi < 2; ++fi)
#pragma unroll
            for (int fj = 0; fj < 4; ++fj) {
                int gr = m0 + wm * 32 + fi * 16;
                int gc = n0 + wn * 64 + fj * 16;
                wmma::store_matrix_sync(&Cb[(size_t)gr * ldc + gc], acc[fi][fj], ldc,
                                        wmma::mem_row_major);
            }
    } else {
        // stage tile in smem; exp + row/col partial sums + coalesced e write
        float* Sf = (float*)sm;   // 128 x 132 fp32 = 67584 B
#pragma unroll
        for (int fi = 0; fi < 2; ++fi)
#pragma unroll
            for (int fj = 0; fj < 4; ++fj) {
                int lr = wm * 32 + fi * 16;
                int lc = wn * 64 + fj * 16;
                wmma::store_matrix_sync(&Sf[lr * 132 + lc], acc[fi][fj], 132,
                                        wmma::mem_row_major);
            }
        __syncthreads();

        // row pass: exp in place + row sums
        {
            int r = tid >> 1, half = tid & 1;
            float* row = Sf + r * 132 + half * 64;
            float s = 0.f;
#pragma unroll 8
            for (int c = 0; c < 64; ++c) {
                float e = __expf(row[c] - SHIFT);
                row[c] = e;
                s += e;
            }
            s += __shfl_xor_sync(0xffffffffu, s, 1);
            if (!half) atomicAdd(&rsum[(size_t)b * Ll + m0 + r], s);
        }
        __syncthreads();

        // col pass: col sums over exp'd tile
        {
            int c = tid >> 1, half = tid & 1;
            float s = 0.f;
#pragma unroll 8
            for (int r = 0; r < 64; ++r)
                s += Sf[(half * 64 + r) * 132 + c];
            s += __shfl_xor_sync(0xffffffffu, s, 1);
            if (!half) atomicAdd(&csum[(size_t)b * Ll + n0 + c], s);
        }
        __syncthreads();

        // coalesced write of e tile
#pragma unroll 4
        for (int it2 = 0; it2 < 16; ++it2) {
            int q  = tid + it2 * 256;      // float4 index in 128x128 tile
            int ii = q >> 5;
            int c4 = (q & 31) * 4;
            float4 v = *(float4*)&Sf[ii * 132 + c4];
            *(float4*)&Cb[(size_t)(m0 + ii) * ldc + n0 + c4] = v;
        }
    }
}

// ---------------------------------------------------------------------------
// Invert sums in place
// ---------------------------------------------------------------------------
__global__ __launch_bounds__(256)
void k_invert(float* __restrict__ rsum, float* __restrict__ csum) {
    int i = blockIdx.x * 256 + threadIdx.x;
    float* p = (i < Bb * Ll) ? (rsum + i) : (csum + i - Bb * Ll);
    *p = 1.0f / *p;
}

// ---------------------------------------------------------------------------
// Normalize: w2 = fp16(e * rsinv[i]), w1 = fp16(e * csinv[j])  (hi only)
// ---------------------------------------------------------------------------
__global__ __launch_bounds__(256)
void k_norm(const float* __restrict__ eatt,
            const float* __restrict__ rsinv, const float* __restrict__ csinv,
            __half* __restrict__ w2hi, __half* __restrict__ w1hi) {
    size_t base = ((size_t)blockIdx.x * 256 + threadIdx.x) * 4;
    int bi = (int)(base >> 10);            // b*Ll + i
    int j  = (int)(base & (Ll - 1));
    int b  = bi >> 10;

    float4 e  = *(const float4*)&eatt[base];
    float  rs = rsinv[bi];
    float4 cs = *(const float4*)&csinv[(size_t)b * Ll + j];

    HF4 h2, h1;
    h2.v[0] = __float2half_rn(e.x * rs);
    h2.v[1] = __float2half_rn(e.y * rs);
    h2.v[2] = __float2half_rn(e.z * rs);
    h2.v[3] = __float2half_rn(e.w * rs);
    h1.v[0] = __float2half_rn(e.x * cs.x);
    h1.v[1] = __float2half_rn(e.y * cs.y);
    h1.v[2] = __float2half_rn(e.z * cs.z);
    h1.v[3] = __float2half_rn(e.w * cs.w);
    *(HF4*)&w2hi[base] = h2;
    *(HF4*)&w1hi[base] = h1;
}

// ---------------------------------------------------------------------------
extern "C" void kernel_launch(void* const* d_in, const int* in_sizes, int n_in,
                              void* d_out, int out_size) {
    const float* in1 = (const float*)d_in[0];
    const float* in2 = (const float*)d_in[1];
    float* out = (float*)d_out;

    const int SMEM_SCORES = 81920;                    // 2 x 40960 (epilogue 67584 fits)
    const int SMEM_OUTA   = 2 * (TILE_KN + TILE_KN);  // 34816
    const int SMEM_OUTB   = 2 * (TILE_MK + TILE_KN);  // 37888
    cudaFuncSetAttribute(gemmw<false, true,  true,  3>, cudaFuncAttributeMaxDynamicSharedMemorySize, SMEM_SCORES);
    cudaFuncSetAttribute(gemmw<true,  false, false, 1>, cudaFuncAttributeMaxDynamicSharedMemorySize, SMEM_OUTA);
    cudaFuncSetAttribute(gemmw<false, false, false, 1>, cudaFuncAttributeMaxDynamicSharedMemorySize, SMEM_OUTB);

    float *eatt, *rsum, *csum;
    __half *i1h, *i1l, *i2h, *i2l, *w2h, *w1h;
    cudaGetSymbolAddress((void**)&eatt, g_eatt);
    cudaGetSymbolAddress((void**)&rsum, g_rsum);
    cudaGetSymbolAddress((void**)&csum, g_csum);
    cudaGetSymbolAddress((void**)&i1h,  g_in1hi);
    cudaGetSymbolAddress((void**)&i1l,  g_in1lo);
    cudaGetSymbolAddress((void**)&i2h,  g_in2hi);
    cudaGetSymbolAddress((void**)&i2l,  g_in2lo);
    cudaGetSymbolAddress((void**)&w2h,  g_w2hi);
    cudaGetSymbolAddress((void**)&w1h,  g_w1hi);

    // 0) zero sum accumulators
    cudaMemsetAsync(rsum, 0, Bb * Ll * sizeof(float));
    cudaMemsetAsync(csum, 0, Bb * Ll * sizeof(float));

    // 1) split inputs to fp16 hi/lo
    int sblk = (int)(((size_t)Bb * Ll * Dd) / (256 * 4));
    k_split2<<<dim3(sblk, 2), 256>>>(in1, in2, i1h, i1l, i2h, i2l);

    // 2) scores GEMM (3 products) + fused exp/row-sum/col-sum epilogue -> eatt
    gemmw<false, true, true, 3><<<dim3(Ll / 128, Ll / 128, Bb), 256, SMEM_SCORES>>>(
        i1h, i1l, i2h, i2l, Dd, Dd, Dd,
        eatt, Ll, (size_t)Ll * Dd, (size_t)Ll * Dd, (size_t)Ll * Ll,
        rsum, csum);

    // 3) invert sums
    k_invert<<<(2 * Bb * Ll) / 256, 256>>>(rsum, csum);

    // 4) normalize to fp16 (hi only), both weight matrices, one eatt read
    int nblk = (int)(((size_t)Bb * Ll * Ll) / (256 * 4));
    k_norm<<<nblk, 256>>>(eatt, rsum, csum, w2h, w1h);

    // 5) outA[b,j,d] = sum_i w1[i,j] * in1[i,d]  (A = w1 col-major, 1 product)
    gemmw<true, false, false, 1><<<dim3(Dd / 128, Ll / 128, Bb), 256, SMEM_OUTA>>>(
        w1h, nullptr, i1h, nullptr, Ll, Dd, Ll,
        out, Dd, (size_t)Ll * Ll, (size_t)Ll * Dd, (size_t)Ll * Dd,
        nullptr, nullptr);

    // 6) outB[b,i,d] = sum_j w2[i,j] * in2[j,d]  (A = w2 row-major, 1 product)
    gemmw<false, false, false, 1><<<dim3(Dd / 128, Ll / 128, Bb), 256, SMEM_OUTB>>>(
        w2h, nullptr, i2h, nullptr, Ll, Dd, Ll,
        out + (size_t)Bb * Ll * Dd, Dd, (size_t)Ll * Ll, (size_t)Ll * Dd, (size_t)Ll * Dd,
        nullptr, nullptr);
}

// round 9
// speedup vs baseline: 4.4681x; 1.0003x over previous
#include <cuda_runtime.h>
#include <cuda_fp16.h>
#include <mma.h>
#include <cstdint>
#include <math.h>

using namespace nvcuda;

#define Bb 32
#define Ll 1024
#define Dd 768
#define SHIFT 120.0f

// ---------------------------------------------------------------------------
// Scratch (device globals; no allocation allowed)
// ---------------------------------------------------------------------------
__device__ float g_eatt[(size_t)Bb * Ll * Ll];   // exp(att - SHIFT)  [i][j]

__device__ __half g_in1hi[(size_t)Bb * Ll * Dd];
__device__ __half g_in1lo[(size_t)Bb * Ll * Dd];
__device__ __half g_in2hi[(size_t)Bb * Ll * Dd];
__device__ __half g_in2lo[(size_t)Bb * Ll * Dd];

__device__ __half g_w2hi[(size_t)Bb * Ll * Ll];   // axis-2 softmax  [i][j]
__device__ __half g_w1hi[(size_t)Bb * Ll * Ll];   // axis-1 softmax  [i][j]

__device__ float g_rsum[Bb * Ll];   // per-row sums -> inverted in place
__device__ float g_csum[Bb * Ll];   // per-col sums -> inverted in place

struct alignas(8) HF4 { __half v[4]; };

__device__ __forceinline__ HF4 split4(const float* vv, HF4& lo) {
    HF4 hi;
#pragma unroll
    for (int k = 0; k < 4; ++k) {
        hi.v[k] = __float2half_rn(vv[k]);
        lo.v[k] = __float2half_rn(vv[k] - __half2float(hi.v[k]));
    }
    return hi;
}

__device__ __forceinline__ uint32_t smem_u32(const void* p) {
    uint32_t a;
    asm("{ .reg .u64 t; cvta.to.shared.u64 t, %1; cvt.u32.u64 %0, t; }"
        : "=r"(a) : "l"(p));
    return a;
}

__device__ __forceinline__ void cp16(uint32_t dst, const void* src) {
    asm volatile("cp.async.cg.shared.global [%0], [%1], 16;" :: "r"(dst), "l"(src));
}
#define CP_COMMIT() asm volatile("cp.async.commit_group;" ::: "memory")
#define CP_WAIT(n)  asm volatile("cp.async.wait_group %0;" :: "n"(n) : "memory")

// ---------------------------------------------------------------------------
// Elementwise split fp32 -> fp16 hi/lo for both inputs.
// Also zeroes rsum/csum (first 64 blocks of y==0) — replaces memsets.
// ---------------------------------------------------------------------------
__global__ __launch_bounds__(256)
void k_split2(const float* __restrict__ in1, const float* __restrict__ in2,
              __half* __restrict__ hi1, __half* __restrict__ lo1,
              __half* __restrict__ hi2, __half* __restrict__ lo2,
              float* __restrict__ rsum, float* __restrict__ csum) {
    if (blockIdx.y == 0 && blockIdx.x < 64) {
        int idx = blockIdx.x * 1024 + threadIdx.x * 4;   // 0..65532
        float4 z = {0.f, 0.f, 0.f, 0.f};
        if (idx < Bb * Ll) *(float4*)&rsum[idx] = z;
        else               *(float4*)&csum[idx - Bb * Ll] = z;
    }
    const float* src = blockIdx.y ? in2 : in1;
    __half* hi = blockIdx.y ? hi2 : hi1;
    __half* lo = blockIdx.y ? lo2 : lo1;
    size_t base = ((size_t)blockIdx.x * 256 + threadIdx.x) * 4;
    float4 v = *(const float4*)&src[base];
    float vv[4] = {v.x, v.y, v.z, v.w};
    HF4 l4; HF4 h4 = split4(vv, l4);
    *(HF4*)&hi[base] = h4;
    *(HF4*)&lo[base] = l4;
}

// ---------------------------------------------------------------------------
// Pipelined WMMA fp16 GEMM. CTA 128x128, KC=32, STAGES-deep cp.async.
//   NPROD=3: scores (A hi/lo row-major, B hi/lo col-major: hh + lh + hl)
//   NPROD=1: outputs (A hi only [col or row major], B hi only row-major)
//   REDUCE: epilogue computes e=exp(v-SHIFT), row/col sums (atomicAdd), writes e.
// ---------------------------------------------------------------------------
#define KC 32
#define AP 40            // [M,K]-tile pitch in halves (80B rows)
#define BP 136           // [K,N]/[K,M]-tile pitch in halves (272B rows)
#define TILE_MK (128 * AP * 2)   // 10240 bytes: 128 rows x KC halves
#define TILE_KN (KC * BP * 2)    // 8704  bytes: KC rows x 128 halves

template <bool A_COL, bool B_COL, bool REDUCE, int NPROD, int STAGES>
__global__ __launch_bounds__(256, 2)
void gemmw(const __half* __restrict__ Ahi, const __half* __restrict__ Alo,
           const __half* __restrict__ Bhi, const __half* __restrict__ Blo,
           int lda, int ldb, int K,
           float* __restrict__ C, int ldc,
           size_t sA, size_t sB, size_t sC,
           float* __restrict__ rsum, float* __restrict__ csum) {
    extern __shared__ char sm[];
    const uint32_t sbase = smem_u32(sm);
    constexpr int ATILE = A_COL ? TILE_KN : TILE_MK;
    constexpr int BTILE = B_COL ? TILE_MK : TILE_KN;
    constexpr int NA = (NPROD == 3) ? 2 : 1;
    constexpr int NB = (NPROD == 3) ? 2 : 1;
    constexpr int STAGE = NA * ATILE + NB * BTILE;

    int tid = threadIdx.x;
    int wid = tid >> 5;
    int wm  = wid & 3;
    int wn  = wid >> 2;
    int b   = blockIdx.z;
    int m0  = blockIdx.y * 128;
    int n0  = blockIdx.x * 128;

    const __half* Ah = Ahi + (size_t)b * sA + (A_COL ? (size_t)m0 : (size_t)m0 * lda);
    const __half* Al = (NPROD == 3) ? (Alo + (size_t)b * sA + (size_t)m0 * lda) : nullptr;
    const __half* Bh = Bhi + (size_t)b * sB + (B_COL ? (size_t)n0 * ldb : (size_t)n0);
    const __half* Bl = (B_COL && NPROD == 3) ? (Blo + (size_t)b * sB + (size_t)n0 * ldb) : nullptr;

    int arow = tid >> 2;            // [M,K] tiles: 0..63 (x2 -> 128 rows)
    int ac16 = (tid & 3) * 8;       // covers KC=32 halves
    int brow = tid >> 4;            // [K,*] tiles: 0..15 (x2 -> 32 rows)
    int bc16 = (tid & 15) * 8;      // covers 128 halves

    auto load_stage = [&](int st, int k0) {
        uint32_t s = sbase + st * STAGE;
        if (!A_COL) {
#pragma unroll
            for (int h = 0; h < 2; ++h) {
                int r = arow + h * 64;
                uint32_t d = s + r * (AP * 2) + ac16 * 2;
                cp16(d, Ah + (size_t)r * lda + k0 + ac16);
                if (NPROD == 3)
                    cp16(d + ATILE, Al + (size_t)r * lda + k0 + ac16);
            }
        } else {
#pragma unroll
            for (int h = 0; h < 2; ++h) {
                int r = brow + h * 16;
                uint32_t d = s + r * (BP * 2) + bc16 * 2;
                cp16(d, Ah + (size_t)(k0 + r) * lda + bc16);
            }
        }
        if (B_COL) {
#pragma unroll
            for (int h = 0; h < 2; ++h) {
                int r = arow + h * 64;
                uint32_t d = s + NA * ATILE + r * (AP * 2) + ac16 * 2;
                cp16(d, Bh + (size_t)r * ldb + k0 + ac16);
                if (NPROD == 3)
                    cp16(d + BTILE, Bl + (size_t)r * ldb + k0 + ac16);
            }
        } else {
#pragma unroll
            for (int h = 0; h < 2; ++h) {
                int r = brow + h * 16;
                uint32_t d = s + NA * ATILE + r * (BP * 2) + bc16 * 2;
                cp16(d, Bh + (size_t)(k0 + r) * ldb + bc16);
            }
        }
    };

    auto compute = [&](int buf, wmma::fragment<wmma::accumulator, 16, 16, 16, float> (&acc)[2][4]) {
        const __half* sA0 = (const __half*)(sm + buf * STAGE);
        const __half* sAl = sA0 + ATILE / 2;
        const __half* sB0 = (const __half*)((const char*)sA0 + NA * ATILE);
        const __half* sBl = sB0 + BTILE / 2;

#pragma unroll
        for (int ks = 0; ks < KC / 16; ++ks) {
            if constexpr (NPROD == 3) {
                wmma::fragment<wmma::matrix_a, 16, 16, 16, __half, wmma::row_major> ah[2], al[2];
#pragma unroll
                for (int fi = 0; fi < 2; ++fi) {
                    int ro = (wm * 32 + fi * 16) * AP + ks * 16;
                    wmma::load_matrix_sync(ah[fi], &sA0[ro], AP);
                    wmma::load_matrix_sync(al[fi], &sAl[ro], AP);
                }
#pragma unroll
                for (int fj = 0; fj < 4; ++fj) {
                    wmma::fragment<wmma::matrix_b, 16, 16, 16, __half, wmma::col_major> bh, bl;
                    int ro = (wn * 64 + fj * 16) * AP + ks * 16;
                    wmma::load_matrix_sync(bh, &sB0[ro], AP);
                    wmma::load_matrix_sync(bl, &sBl[ro], AP);
#pragma unroll
                    for (int fi = 0; fi < 2; ++fi) {
                        wmma::mma_sync(acc[fi][fj], ah[fi], bh, acc[fi][fj]);
                        wmma::mma_sync(acc[fi][fj], al[fi], bh, acc[fi][fj]);
                        wmma::mma_sync(acc[fi][fj], ah[fi], bl, acc[fi][fj]);
                    }
                }
            } else if constexpr (A_COL) {
                wmma::fragment<wmma::matrix_a, 16, 16, 16, __half, wmma::col_major> ah[2];
#pragma unroll
                for (int fi = 0; fi < 2; ++fi) {
                    int ro = (ks * 16) * BP + wm * 32 + fi * 16;
                    wmma::load_matrix_sync(ah[fi], &sA0[ro], BP);
                }
#pragma unroll
                for (int fj = 0; fj < 4; ++fj) {
                    wmma::fragment<wmma::matrix_b, 16, 16, 16, __half, wmma::row_major> bh;
                    int ro = (ks * 16) * BP + wn * 64 + fj * 16;
                    wmma::load_matrix_sync(bh, &sB0[ro], BP);
#pragma unroll
                    for (int fi = 0; fi < 2; ++fi)
                        wmma::mma_sync(acc[fi][fj], ah[fi], bh, acc[fi][fj]);
                }
            } else {
                wmma::fragment<wmma::matrix_a, 16, 16, 16, __half, wmma::row_major> ah[2];
#pragma unroll
                for (int fi = 0; fi < 2; ++fi) {
                    int ro = (wm * 32 + fi * 16) * AP + ks * 16;
                    wmma::load_matrix_sync(ah[fi], &sA0[ro], AP);
                }
#pragma unroll
                for (int fj = 0; fj < 4; ++fj) {
                    wmma::fragment<wmma::matrix_b, 16, 16, 16, __half, wmma::row_major> bh;
                    int ro = (ks * 16) * BP + wn * 64 + fj * 16;
                    wmma::load_matrix_sync(bh, &sB0[ro], BP);
#pragma unroll
                    for (int fi = 0; fi < 2; ++fi)
                        wmma::mma_sync(acc[fi][fj], ah[fi], bh, acc[fi][fj]);
                }
            }
        }
    };

    wmma::fragment<wmma::accumulator, 16, 16, 16, float> acc[2][4];
#pragma unroll
    for (int i = 0; i < 2; ++i)
#pragma unroll
        for (int j = 0; j < 4; ++j)
            wmma::fill_fragment(acc[i][j], 0.0f);

    const int NK = K / KC;

    if constexpr (STAGES == 2) {
        load_stage(0, 0);
        CP_COMMIT();
        for (int it = 0; it < NK; ++it) {
            if (it + 1 < NK) {
                load_stage((it + 1) & 1, (it + 1) * KC);
                CP_COMMIT();
                CP_WAIT(1);
            } else {
                CP_WAIT(0);
            }
            __syncthreads();
            compute(it & 1, acc);
            __syncthreads();
        }
    } else {
        // 3-stage: loads for it+1 and it+2 in flight during compute(it)
        load_stage(0, 0);
        CP_COMMIT();
        load_stage(1, KC);
        CP_COMMIT();
        int buf = 0;
        for (int it = 0; it < NK; ++it) {
            if (it + 1 < NK) CP_WAIT(1);
            else             CP_WAIT(0);
            __syncthreads();
            if (it + 2 < NK) {
                load_stage((it + 2) % 3, (it + 2) * KC);
                CP_COMMIT();
            }
            compute(buf, acc);
            buf = (buf + 1 == 3) ? 0 : buf + 1;
        }
    }

    // --- Epilogue ---
    float* Cb = C + (size_t)b * sC;
    if constexpr (!REDUCE) {
#pragma unroll
        for (int fi = 0; fi < 2; ++fi)
#pragma unroll
            for (int fj = 0; fj < 4; ++fj) {
                int gr = m0 + wm * 32 + fi * 16;
                int gc = n0 + wn * 64 + fj * 16;
                wmma::store_matrix_sync(&Cb[(size_t)gr * ldc + gc], acc[fi][fj], ldc,
                                        wmma::mem_row_major);
            }
    } else {
        __syncthreads();   // 3-stage path exits loop without trailing sync
        float* Sf = (float*)sm;   // 128 x 132 fp32 = 67584 B
#pragma unroll
        for (int fi = 0; fi < 2; ++fi)
#pragma unroll
            for (int fj = 0; fj < 4; ++fj) {
                int lr = wm * 32 + fi * 16;
                int lc = wn * 64 + fj * 16;
                wmma::store_matrix_sync(&Sf[lr * 132 + lc], acc[fi][fj], 132,
                                        wmma::mem_row_major);
            }
        __syncthreads();

        // row pass: exp in place + row sums
        {
            int r = tid >> 1, half = tid & 1;
            float* row = Sf + r * 132 + half * 64;
            float s = 0.f;
#pragma unroll 8
            for (int c = 0; c < 64; ++c) {
                float e = __expf(row[c] - SHIFT);
                row[c] = e;
                s += e;
            }
            s += __shfl_xor_sync(0xffffffffu, s, 1);
            if (!half) atomicAdd(&rsum[(size_t)b * Ll + m0 + r], s);
        }
        __syncthreads();

        // col pass: col sums over exp'd tile
        {
            int c = tid >> 1, half = tid & 1;
            float s = 0.f;
#pragma unroll 8
            for (int r = 0; r < 64; ++r)
                s += Sf[(half * 64 + r) * 132 + c];
            s += __shfl_xor_sync(0xffffffffu, s, 1);
            if (!half) atomicAdd(&csum[(size_t)b * Ll + n0 + c], s);
        }
        __syncthreads();

        // coalesced write of e tile
#pragma unroll 4
        for (int it2 = 0; it2 < 16; ++it2) {
            int q  = tid + it2 * 256;
            int ii = q >> 5;
            int c4 = (q & 31) * 4;
            float4 v = *(float4*)&Sf[ii * 132 + c4];
            *(float4*)&Cb[(size_t)(m0 + ii) * ldc + n0 + c4] = v;
        }
    }
}

// ---------------------------------------------------------------------------
// Invert sums in place
// ---------------------------------------------------------------------------
__global__ __launch_bounds__(256)
void k_invert(float* __restrict__ rsum, float* __restrict__ csum) {
    int i = blockIdx.x * 256 + threadIdx.x;
    float* p = (i < Bb * Ll) ? (rsum + i) : (csum + i - Bb * Ll);
    *p = 1.0f / *p;
}

// ---------------------------------------------------------------------------
// Normalize: w2 = fp16(e * rsinv[i]), w1 = fp16(e * csinv[j])  (hi only)
// ---------------------------------------------------------------------------
__global__ __launch_bounds__(256)
void k_norm(const float* __restrict__ eatt,
            const float* __restrict__ rsinv, const float* __restrict__ csinv,
            __half* __restrict__ w2hi, __half* __restrict__ w1hi) {
    size_t base = ((size_t)blockIdx.x * 256 + threadIdx.x) * 4;
    int bi = (int)(base >> 10);            // b*Ll + i
    int j  = (int)(base & (Ll - 1));
    int b  = bi >> 10;

    float4 e  = *(const float4*)&eatt[base];
    float  rs = rsinv[bi];
    float4 cs = *(const float4*)&csinv[(size_t)b * Ll + j];

    HF4 h2, h1;
    h2.v[0] = __float2half_rn(e.x * rs);
    h2.v[1] = __float2half_rn(e.y * rs);
    h2.v[2] = __float2half_rn(e.z * rs);
    h2.v[3] = __float2half_rn(e.w * rs);
    h1.v[0] = __float2half_rn(e.x * cs.x);
    h1.v[1] = __float2half_rn(e.y * cs.y);
    h1.v[2] = __float2half_rn(e.z * cs.z);
    h1.v[3] = __float2half_rn(e.w * cs.w);
    *(HF4*)&w2hi[base] = h2;
    *(HF4*)&w1hi[base] = h1;
}

// ---------------------------------------------------------------------------
extern "C" void kernel_launch(void* const* d_in, const int* in_sizes, int n_in,
                              void* d_out, int out_size) {
    const float* in1 = (const float*)d_in[0];
    const float* in2 = (const float*)d_in[1];
    float* out = (float*)d_out;

    const int SMEM_SCORES = 81920;                    // 2 x 40960 (epilogue 67584 fits)
    const int SMEM_OUTA   = 3 * (TILE_KN + TILE_KN);  // 52224
    const int SMEM_OUTB   = 3 * (TILE_MK + TILE_KN);  // 56832
    cudaFuncSetAttribute(gemmw<false, true,  true,  3, 2>, cudaFuncAttributeMaxDynamicSharedMemorySize, SMEM_SCORES);
    cudaFuncSetAttribute(gemmw<true,  false, false, 1, 3>, cudaFuncAttributeMaxDynamicSharedMemorySize, SMEM_OUTA);
    cudaFuncSetAttribute(gemmw<false, false, false, 1, 3>, cudaFuncAttributeMaxDynamicSharedMemorySize, SMEM_OUTB);

    float *eatt, *rsum, *csum;
    __half *i1h, *i1l, *i2h, *i2l, *w2h, *w1h;
    cudaGetSymbolAddress((void**)&eatt, g_eatt);
    cudaGetSymbolAddress((void**)&rsum, g_rsum);
    cudaGetSymbolAddress((void**)&csum, g_csum);
    cudaGetSymbolAddress((void**)&i1h,  g_in1hi);
    cudaGetSymbolAddress((void**)&i1l,  g_in1lo);
    cudaGetSymbolAddress((void**)&i2h,  g_in2hi);
    cudaGetSymbolAddress((void**)&i2l,  g_in2lo);
    cudaGetSymbolAddress((void**)&w2h,  g_w2hi);
    cudaGetSymbolAddress((void**)&w1h,  g_w1hi);

    // 1) split inputs to fp16 hi/lo (+ zero rsum/csum)
    int sblk = (int)(((size_t)Bb * Ll * Dd) / (256 * 4));
    k_split2<<<dim3(sblk, 2), 256>>>(in1, in2, i1h, i1l, i2h, i2l, rsum, csum);

    // 2) scores GEMM (3 products) + fused exp/row-sum/col-sum epilogue -> eatt
    gemmw<false, true, true, 3, 2><<<dim3(Ll / 128, Ll / 128, Bb), 256, SMEM_SCORES>>>(
        i1h, i1l, i2h, i2l, Dd, Dd, Dd,
        eatt, Ll, (size_t)Ll * Dd, (size_t)Ll * Dd, (size_t)Ll * Ll,
        rsum, csum);

    // 3) invert sums
    k_invert<<<(2 * Bb * Ll) / 256, 256>>>(rsum, csum);

    // 4) normalize to fp16 (hi only), both weight matrices, one eatt read
    int nblk = (int)(((size_t)Bb * Ll * Ll) / (256 * 4));
    k_norm<<<nblk, 256>>>(eatt, rsum, csum, w2h, w1h);

    // 5) outA[b,j,d] = sum_i w1[i,j] * in1[i,d]  (A = w1 col-major, 1 product, 3-stage)
    gemmw<true, false, false, 1, 3><<<dim3(Dd / 128, Ll / 128, Bb), 256, SMEM_OUTA>>>(
        w1h, nullptr, i1h, nullptr, Ll, Dd, Ll,
        out, Dd, (size_t)Ll * Ll, (size_t)Ll * Dd, (size_t)Ll * Dd,
        nullptr, nullptr);

    // 6) outB[b,i,d] = sum_j w2[i,j] * in2[j,d]  (A = w2 row-major, 1 product, 3-stage)
    gemmw<false, false, false, 1, 3><<<dim3(Dd / 128, Ll / 128, Bb), 256, SMEM_OUTB>>>(
        w2h, nullptr, i2h, nullptr, Ll, Dd, Ll,
        out + (size_t)Bb * Ll * Dd, Dd, (size_t)Ll * Ll, (size_t)Ll * Dd, (size_t)Ll * Dd,
        nullptr, nullptr);
}

// round 10
// speedup vs baseline: 4.6757x; 1.0465x over previous
#include <cuda_runtime.h>
#include <cuda_fp16.h>
#include <mma.h>
#include <cstdint>
#include <math.h>

using namespace nvcuda;

#define Bb 32
#define Ll 1024
#define Dd 768
#define SHIFT 120.0f

// ---------------------------------------------------------------------------
// Scratch (device globals; no allocation allowed)
// ---------------------------------------------------------------------------
__device__ float g_eatt[(size_t)Bb * Ll * Ll];   // exp(att - SHIFT)  [i][j]

__device__ __half g_in1hi[(size_t)Bb * Ll * Dd];
__device__ __half g_in1lo[(size_t)Bb * Ll * Dd];
__device__ __half g_in2hi[(size_t)Bb * Ll * Dd];
__device__ __half g_in2lo[(size_t)Bb * Ll * Dd];

__device__ __half g_w2hi[(size_t)Bb * Ll * Ll];   // axis-2 softmax  [i][j]
__device__ __half g_w1hi[(size_t)Bb * Ll * Ll];   // axis-1 softmax  [i][j]

__device__ float g_rsum[Bb * Ll];   // per-row sums -> inverted in place
__device__ float g_csum[Bb * Ll];   // per-col sums -> inverted in place

struct alignas(8) HF4 { __half v[4]; };

__device__ __forceinline__ HF4 split4(const float* vv, HF4& lo) {
    HF4 hi;
#pragma unroll
    for (int k = 0; k < 4; ++k) {
        hi.v[k] = __float2half_rn(vv[k]);
        lo.v[k] = __float2half_rn(vv[k] - __half2float(hi.v[k]));
    }
    return hi;
}

__device__ __forceinline__ uint32_t smem_u32(const void* p) {
    uint32_t a;
    asm("{ .reg .u64 t; cvta.to.shared.u64 t, %1; cvt.u32.u64 %0, t; }"
        : "=r"(a) : "l"(p));
    return a;
}

__device__ __forceinline__ void cp16(uint32_t dst, const void* src) {
    asm volatile("cp.async.cg.shared.global [%0], [%1], 16;" :: "r"(dst), "l"(src));
}
#define CP_COMMIT() asm volatile("cp.async.commit_group;" ::: "memory")
#define CP_WAIT(n)  asm volatile("cp.async.wait_group %0;" :: "n"(n) : "memory")

// ---------------------------------------------------------------------------
// Elementwise split fp32 -> fp16 hi/lo for both inputs; zeroes rsum/csum.
// ---------------------------------------------------------------------------
__global__ __launch_bounds__(256)
void k_split2(const float* __restrict__ in1, const float* __restrict__ in2,
              __half* __restrict__ hi1, __half* __restrict__ lo1,
              __half* __restrict__ hi2, __half* __restrict__ lo2,
              float* __restrict__ rsum, float* __restrict__ csum) {
    if (blockIdx.y == 0 && blockIdx.x < 64) {
        int idx = blockIdx.x * 1024 + threadIdx.x * 4;
        float4 z = {0.f, 0.f, 0.f, 0.f};
        if (idx < Bb * Ll) *(float4*)&rsum[idx] = z;
        else               *(float4*)&csum[idx - Bb * Ll] = z;
    }
    const float* src = blockIdx.y ? in2 : in1;
    __half* hi = blockIdx.y ? hi2 : hi1;
    __half* lo = blockIdx.y ? lo2 : lo1;
    size_t base = ((size_t)blockIdx.x * 256 + threadIdx.x) * 4;
    float4 v = *(const float4*)&src[base];
    float vv[4] = {v.x, v.y, v.z, v.w};
    HF4 l4; HF4 h4 = split4(vv, l4);
    *(HF4*)&hi[base] = h4;
    *(HF4*)&lo[base] = l4;
}

// ---------------------------------------------------------------------------
// Scores GEMM: 3-product fp16 (hh+lh+hl), CTA 128x128, KC=32, 2-stage.
// Epilogue: e = exp(v-SHIFT), row/col sums via atomicAdd, writes e.
// ---------------------------------------------------------------------------
#define KC 32
#define AP 40            // [M,K]-tile pitch in halves (80B rows)
#define BP 136           // [K,N]-tile pitch in halves (272B rows)
#define TILE_MK (128 * AP * 2)   // 10240 bytes
#define S_STAGE (4 * TILE_MK)    // 40960 bytes (Ahi,Alo,Bhi,Blo)

__global__ __launch_bounds__(256, 2)
void k_scores(const __half* __restrict__ Ahi, const __half* __restrict__ Alo,
              const __half* __restrict__ Bhi, const __half* __restrict__ Blo,
              float* __restrict__ C,
              float* __restrict__ rsum, float* __restrict__ csum) {
    extern __shared__ char sm[];
    const uint32_t sbase = smem_u32(sm);

    int tid = threadIdx.x;
    int wid = tid >> 5;
    int wm  = wid & 3;
    int wn  = wid >> 2;
    int b   = blockIdx.z;
    int m0  = blockIdx.y * 128;
    int n0  = blockIdx.x * 128;

    const __half* Ah = Ahi + (size_t)b * Ll * Dd + (size_t)m0 * Dd;
    const __half* Al = Alo + (size_t)b * Ll * Dd + (size_t)m0 * Dd;
    const __half* Bh = Bhi + (size_t)b * Ll * Dd + (size_t)n0 * Dd;
    const __half* Bl = Blo + (size_t)b * Ll * Dd + (size_t)n0 * Dd;

    int arow = tid >> 2;            // 0..63 (x2 -> 128 rows)
    int ac16 = (tid & 3) * 8;       // covers KC=32 halves

    auto load_stage = [&](int st, int k0) {
        uint32_t s = sbase + st * S_STAGE;
#pragma unroll
        for (int h = 0; h < 2; ++h) {
            int r = arow + h * 64;
            uint32_t d = s + r * (AP * 2) + ac16 * 2;
            cp16(d,                Ah + (size_t)r * Dd + k0 + ac16);
            cp16(d + TILE_MK,      Al + (size_t)r * Dd + k0 + ac16);
            cp16(d + 2 * TILE_MK,  Bh + (size_t)r * Dd + k0 + ac16);
            cp16(d + 3 * TILE_MK,  Bl + (size_t)r * Dd + k0 + ac16);
        }
    };

    wmma::fragment<wmma::accumulator, 16, 16, 16, float> acc[2][4];
#pragma unroll
    for (int i = 0; i < 2; ++i)
#pragma unroll
        for (int j = 0; j < 4; ++j)
            wmma::fill_fragment(acc[i][j], 0.0f);

    const int NK = Dd / KC;
    load_stage(0, 0);
    CP_COMMIT();

    for (int it = 0; it < NK; ++it) {
        if (it + 1 < NK) {
            load_stage((it + 1) & 1, (it + 1) * KC);
            CP_COMMIT();
            CP_WAIT(1);
        } else {
            CP_WAIT(0);
        }
        __syncthreads();

        const __half* sA0 = (const __half*)(sm + (it & 1) * S_STAGE);
        const __half* sAl = sA0 + TILE_MK / 2;
        const __half* sB0 = sA0 + TILE_MK;
        const __half* sBl = sA0 + 3 * TILE_MK / 2;

#pragma unroll
        for (int ks = 0; ks < KC / 16; ++ks) {
            wmma::fragment<wmma::matrix_a, 16, 16, 16, __half, wmma::row_major> ah[2], al[2];
#pragma unroll
            for (int fi = 0; fi < 2; ++fi) {
                int ro = (wm * 32 + fi * 16) * AP + ks * 16;
                wmma::load_matrix_sync(ah[fi], &sA0[ro], AP);
                wmma::load_matrix_sync(al[fi], &sAl[ro], AP);
            }
#pragma unroll
            for (int fj = 0; fj < 4; ++fj) {
                wmma::fragment<wmma::matrix_b, 16, 16, 16, __half, wmma::col_major> bh, bl;
                int ro = (wn * 64 + fj * 16) * AP + ks * 16;
                wmma::load_matrix_sync(bh, &sB0[ro], AP);
                wmma::load_matrix_sync(bl, &sBl[ro], AP);
#pragma unroll
                for (int fi = 0; fi < 2; ++fi) {
                    wmma::mma_sync(acc[fi][fj], ah[fi], bh, acc[fi][fj]);
                    wmma::mma_sync(acc[fi][fj], al[fi], bh, acc[fi][fj]);
                    wmma::mma_sync(acc[fi][fj], ah[fi], bl, acc[fi][fj]);
                }
            }
        }
        __syncthreads();
    }

    // --- Epilogue: exp + row/col sums + e write ---
    float* Cb = C + (size_t)b * Ll * Ll;
    float* Sf = (float*)sm;   // 128 x 132 fp32 = 67584 B
#pragma unroll
    for (int fi = 0; fi < 2; ++fi)
#pragma unroll
        for (int fj = 0; fj < 4; ++fj) {
            int lr = wm * 32 + fi * 16;
            int lc = wn * 64 + fj * 16;
            wmma::store_matrix_sync(&Sf[lr * 132 + lc], acc[fi][fj], 132,
                                    wmma::mem_row_major);
        }
    __syncthreads();

    {   // row pass: exp in place + row sums
        int r = tid >> 1, half = tid & 1;
        float* row = Sf + r * 132 + half * 64;
        float s = 0.f;
#pragma unroll 8
        for (int c = 0; c < 64; ++c) {
            float e = __expf(row[c] - SHIFT);
            row[c] = e;
            s += e;
        }
        s += __shfl_xor_sync(0xffffffffu, s, 1);
        if (!half) atomicAdd(&rsum[(size_t)b * Ll + m0 + r], s);
    }
    __syncthreads();

    {   // col pass
        int c = tid >> 1, half = tid & 1;
        float s = 0.f;
#pragma unroll 8
        for (int r = 0; r < 64; ++r)
            s += Sf[(half * 64 + r) * 132 + c];
        s += __shfl_xor_sync(0xffffffffu, s, 1);
        if (!half) atomicAdd(&csum[(size_t)b * Ll + n0 + c], s);
    }
    __syncthreads();

#pragma unroll 4
    for (int it2 = 0; it2 < 16; ++it2) {
        int q  = tid + it2 * 256;
        int ii = q >> 5;
        int c4 = (q & 31) * 4;
        float4 v = *(float4*)&Sf[ii * 132 + c4];
        *(float4*)&Cb[(size_t)(m0 + ii) * Ll + n0 + c4] = v;
    }
}

// ---------------------------------------------------------------------------
// Invert sums in place
// ---------------------------------------------------------------------------
__global__ __launch_bounds__(256)
void k_invert(float* __restrict__ rsum, float* __restrict__ csum) {
    int i = blockIdx.x * 256 + threadIdx.x;
    float* p = (i < Bb * Ll) ? (rsum + i) : (csum + i - Bb * Ll);
    *p = 1.0f / *p;
}

// ---------------------------------------------------------------------------
// Normalize: w2 = fp16(e * rsinv[i]), w1 = fp16(e * csinv[j])
// ---------------------------------------------------------------------------
__global__ __launch_bounds__(256)
void k_norm(const float* __restrict__ eatt,
            const float* __restrict__ rsinv, const float* __restrict__ csinv,
            __half* __restrict__ w2hi, __half* __restrict__ w1hi) {
    size_t base = ((size_t)blockIdx.x * 256 + threadIdx.x) * 4;
    int bi = (int)(base >> 10);            // b*Ll + i
    int j  = (int)(base & (Ll - 1));
    int b  = bi >> 10;

    float4 e  = *(const float4*)&eatt[base];
    float  rs = rsinv[bi];
    float4 cs = *(const float4*)&csinv[(size_t)b * Ll + j];

    HF4 h2, h1;
    h2.v[0] = __float2half_rn(e.x * rs);
    h2.v[1] = __float2half_rn(e.y * rs);
    h2.v[2] = __float2half_rn(e.z * rs);
    h2.v[3] = __float2half_rn(e.w * rs);
    h1.v[0] = __float2half_rn(e.x * cs.x);
    h1.v[1] = __float2half_rn(e.y * cs.y);
    h1.v[2] = __float2half_rn(e.z * cs.z);
    h1.v[3] = __float2half_rn(e.w * cs.w);
    *(HF4*)&w2hi[base] = h2;
    *(HF4*)&w1hi[base] = h1;
}

// ---------------------------------------------------------------------------
// Merged output GEMMs. KC=64, 2-stage cp.async, 1 product.
//   A_COL=true  (outA): A = w1 read as [K=i, M=j] col-major frags, B = in1 [K,N]
//   A_COL=false (outB): A = w2 [M=i, K=j] row-major frags,        B = in2 [K,N]
// ---------------------------------------------------------------------------
#define KC2 64
#define AP2 72                     // [M,K] tile pitch in halves (144B rows)
#define TILE_A2 (128 * AP2 * 2)    // 18432 bytes: 128 x 64 halves
#define TILE_K2 (KC2 * BP * 2)     // 17408 bytes: 64 x 128 halves (pitch 136)
#define O_STAGE (TILE_A2 + TILE_K2)  // 35840 (outB); outA uses 2*TILE_K2=34816

template <bool A_COL>
__device__ __forceinline__
void out_body(const __half* __restrict__ W, const __half* __restrict__ IN,
              float* __restrict__ out, int b, char* sm) {
    const uint32_t sbase = smem_u32(sm);
    constexpr int ATILE = A_COL ? TILE_K2 : TILE_A2;
    constexpr int STAGE = O_STAGE;   // common stride for both variants

    int tid = threadIdx.x;
    int wid = tid >> 5;
    int wm  = wid & 3;
    int wn  = wid >> 2;
    int m0  = blockIdx.y * 128;
    int n0  = blockIdx.x * 128;

    const __half* Ag = W  + (size_t)b * Ll * Ll + (A_COL ? (size_t)m0 : (size_t)m0 * Ll);
    const __half* Bg = IN + (size_t)b * Ll * Dd + n0;

    // load maps
    int arow = tid >> 3;            // 0..31 (x4 -> 128 rows), 64-half cols
    int ac16 = (tid & 7) * 8;       // 0..56
    int brow = tid >> 4;            // 0..15 (x4 -> 64 rows), 128-half cols
    int bc16 = (tid & 15) * 8;      // 0..120

    auto load_stage = [&](int st, int k0) {
        uint32_t s = sbase + st * STAGE;
        if (!A_COL) {
#pragma unroll
            for (int h = 0; h < 4; ++h) {
                int r = arow + h * 32;
                cp16(s + r * (AP2 * 2) + ac16 * 2, Ag + (size_t)r * Ll + k0 + ac16);
            }
        } else {
#pragma unroll
            for (int h = 0; h < 4; ++h) {
                int r = brow + h * 16;
                cp16(s + r * (BP * 2) + bc16 * 2, Ag + (size_t)(k0 + r) * Ll + bc16);
            }
        }
#pragma unroll
        for (int h = 0; h < 4; ++h) {
            int r = brow + h * 16;
            cp16(s + ATILE + r * (BP * 2) + bc16 * 2, Bg + (size_t)(k0 + r) * Dd + bc16);
        }
    };

    wmma::fragment<wmma::accumulator, 16, 16, 16, float> acc[2][4];
#pragma unroll
    for (int i = 0; i < 2; ++i)
#pragma unroll
        for (int j = 0; j < 4; ++j)
            wmma::fill_fragment(acc[i][j], 0.0f);

    const int NK = Ll / KC2;   // 16
    load_stage(0, 0);
    CP_COMMIT();

    for (int it = 0; it < NK; ++it) {
        if (it + 1 < NK) {
            load_stage((it + 1) & 1, (it + 1) * KC2);
            CP_COMMIT();
            CP_WAIT(1);
        } else {
            CP_WAIT(0);
        }
        __syncthreads();

        const __half* sA0 = (const __half*)(sm + (it & 1) * STAGE);
        const __half* sB0 = (const __half*)((const char*)sA0 + ATILE);

#pragma unroll
        for (int ks = 0; ks < KC2 / 16; ++ks) {
            wmma::fragment<wmma::matrix_b, 16, 16, 16, __half, wmma::row_major> bh[4];
#pragma unroll
            for (int fj = 0; fj < 4; ++fj) {
                int ro = (ks * 16) * BP + wn * 64 + fj * 16;
                wmma::load_matrix_sync(bh[fj], &sB0[ro], BP);
            }
            if constexpr (A_COL) {
                wmma::fragment<wmma::matrix_a, 16, 16, 16, __half, wmma::col_major> ah[2];
#pragma unroll
                for (int fi = 0; fi < 2; ++fi) {
                    int ro = (ks * 16) * BP + wm * 32 + fi * 16;
                    wmma::load_matrix_sync(ah[fi], &sA0[ro], BP);
                }
#pragma unroll
                for (int fj = 0; fj < 4; ++fj)
#pragma unroll
                    for (int fi = 0; fi < 2; ++fi)
                        wmma::mma_sync(acc[fi][fj], ah[fi], bh[fj], acc[fi][fj]);
            } else {
                wmma::fragment<wmma::matrix_a, 16, 16, 16, __half, wmma::row_major> ah[2];
#pragma unroll
                for (int fi = 0; fi < 2; ++fi) {
                    int ro = (wm * 32 + fi * 16) * AP2 + ks * 16;
                    wmma::load_matrix_sync(ah[fi], &sA0[ro], AP2);
                }
#pragma unroll
                for (int fj = 0; fj < 4; ++fj)
#pragma unroll
                    for (int fi = 0; fi < 2; ++fi)
                        wmma::mma_sync(acc[fi][fj], ah[fi], bh[fj], acc[fi][fj]);
            }
        }
        __syncthreads();
    }

    float* Cb = out + (size_t)b * Ll * Dd;
#pragma unroll
    for (int fi = 0; fi < 2; ++fi)
#pragma unroll
        for (int fj = 0; fj < 4; ++fj) {
            int gr = m0 + wm * 32 + fi * 16;
            int gc = n0 + wn * 64 + fj * 16;
            wmma::store_matrix_sync(&Cb[(size_t)gr * Dd + gc], acc[fi][fj], Dd,
                                    wmma::mem_row_major);
        }
}

__global__ __launch_bounds__(256, 2)
void k_out(const __half* __restrict__ w1, const __half* __restrict__ w2,
           const __half* __restrict__ i1h, const __half* __restrict__ i2h,
           float* __restrict__ out) {
    extern __shared__ char sm[];
    int z = blockIdx.z;
    if (z < Bb) out_body<true >(w1, i1h, out, z, sm);
    else        out_body<false>(w2, i2h, out + (size_t)Bb * Ll * Dd, z - Bb, sm);
}

// ---------------------------------------------------------------------------
extern "C" void kernel_launch(void* const* d_in, const int* in_sizes, int n_in,
                              void* d_out, int out_size) {
    const float* in1 = (const float*)d_in[0];
    const float* in2 = (const float*)d_in[1];
    float* out = (float*)d_out;

    const int SMEM_SCORES = 2 * S_STAGE;   // 81920 (epilogue 67584 fits)
    const int SMEM_OUT    = 2 * O_STAGE;   // 71680
    cudaFuncSetAttribute(k_scores, cudaFuncAttributeMaxDynamicSharedMemorySize, SMEM_SCORES);
    cudaFuncSetAttribute(k_out,    cudaFuncAttributeMaxDynamicSharedMemorySize, SMEM_OUT);

    float *eatt, *rsum, *csum;
    __half *i1h, *i1l, *i2h, *i2l, *w2h, *w1h;
    cudaGetSymbolAddress((void**)&eatt, g_eatt);
    cudaGetSymbolAddress((void**)&rsum, g_rsum);
    cudaGetSymbolAddress((void**)&csum, g_csum);
    cudaGetSymbolAddress((void**)&i1h,  g_in1hi);
    cudaGetSymbolAddress((void**)&i1l,  g_in1lo);
    cudaGetSymbolAddress((void**)&i2h,  g_in2hi);
    cudaGetSymbolAddress((void**)&i2l,  g_in2lo);
    cudaGetSymbolAddress((void**)&w2h,  g_w2hi);
    cudaGetSymbolAddress((void**)&w1h,  g_w1hi);

    // 1) split inputs to fp16 hi/lo (+ zero rsum/csum)
    int sblk = (int)(((size_t)Bb * Ll * Dd) / (256 * 4));
    k_split2<<<dim3(sblk, 2), 256>>>(in1, in2, i1h, i1l, i2h, i2l, rsum, csum);

    // 2) scores GEMM (3 products) + fused exp/row-sum/col-sum epilogue -> eatt
    k_scores<<<dim3(Ll / 128, Ll / 128, Bb), 256, SMEM_SCORES>>>(
        i1h, i1l, i2h, i2l, eatt, rsum, csum);

    // 3) invert sums
    k_invert<<<(2 * Bb * Ll) / 256, 256>>>(rsum, csum);

    // 4) normalize to fp16 (hi only)
    int nblk = (int)(((size_t)Bb * Ll * Ll) / (256 * 4));
    k_norm<<<nblk, 256>>>(eatt, rsum, csum, w2h, w1h);

    // 5+6) merged output GEMMs: z<32 -> outA (w1^T @ in1), else outB (w2 @ in2)
    k_out<<<dim3(Dd / 128, Ll / 128, 2 * Bb), 256, SMEM_OUT>>>(
        w1h, w2h, i1h, i2h, out);
}

// round 11
// speedup vs baseline: 4.7298x; 1.0116x over previous
#include <cuda_runtime.h>
#include <cuda_fp16.h>
#include <mma.h>
#include <cstdint>
#include <math.h>

using namespace nvcuda;

#define Bb 32
#define Ll 1024
#define Dd 768
#define SHIFT 120.0f

// ---------------------------------------------------------------------------
// Scratch (device globals; no allocation allowed)
// ---------------------------------------------------------------------------
__device__ float g_eatt[(size_t)Bb * Ll * Ll];   // exp(att - SHIFT)  [i][j]

__device__ __half g_in1hi[(size_t)Bb * Ll * Dd];
__device__ __half g_in1lo[(size_t)Bb * Ll * Dd];
__device__ __half g_in2hi[(size_t)Bb * Ll * Dd];
__device__ __half g_in2lo[(size_t)Bb * Ll * Dd];

__device__ float g_rsum[Bb * Ll];   // per-row sums -> inverted in place
__device__ float g_csum[Bb * Ll];   // per-col sums -> inverted in place

struct alignas(8) HF4 { __half v[4]; };

__device__ __forceinline__ HF4 split4(const float* vv, HF4& lo) {
    HF4 hi;
#pragma unroll
    for (int k = 0; k < 4; ++k) {
        hi.v[k] = __float2half_rn(vv[k]);
        lo.v[k] = __float2half_rn(vv[k] - __half2float(hi.v[k]));
    }
    return hi;
}

__device__ __forceinline__ uint32_t smem_u32(const void* p) {
    uint32_t a;
    asm("{ .reg .u64 t; cvta.to.shared.u64 t, %1; cvt.u32.u64 %0, t; }"
        : "=r"(a) : "l"(p));
    return a;
}

__device__ __forceinline__ void cp16(uint32_t dst, const void* src) {
    asm volatile("cp.async.cg.shared.global [%0], [%1], 16;" :: "r"(dst), "l"(src));
}
#define CP_COMMIT() asm volatile("cp.async.commit_group;" ::: "memory")
#define CP_WAIT(n)  asm volatile("cp.async.wait_group %0;" :: "n"(n) : "memory")

__device__ __forceinline__ uint32_t pack2(float a, float b) {
    __half2 h = __floats2half2_rn(a, b);
    return *reinterpret_cast<uint32_t*>(&h);
}

// ---------------------------------------------------------------------------
// Elementwise split fp32 -> fp16 hi/lo for both inputs; zeroes rsum/csum.
// ---------------------------------------------------------------------------
__global__ __launch_bounds__(256)
void k_split2(const float* __restrict__ in1, const float* __restrict__ in2,
              __half* __restrict__ hi1, __half* __restrict__ lo1,
              __half* __restrict__ hi2, __half* __restrict__ lo2,
              float* __restrict__ rsum, float* __restrict__ csum) {
    if (blockIdx.y == 0 && blockIdx.x < 64) {
        int idx = blockIdx.x * 1024 + threadIdx.x * 4;
        float4 z = {0.f, 0.f, 0.f, 0.f};
        if (idx < Bb * Ll) *(float4*)&rsum[idx] = z;
        else               *(float4*)&csum[idx - Bb * Ll] = z;
    }
    const float* src = blockIdx.y ? in2 : in1;
    __half* hi = blockIdx.y ? hi2 : hi1;
    __half* lo = blockIdx.y ? lo2 : lo1;
    size_t base = ((size_t)blockIdx.x * 256 + threadIdx.x) * 4;
    float4 v = *(const float4*)&src[base];
    float vv[4] = {v.x, v.y, v.z, v.w};
    HF4 l4; HF4 h4 = split4(vv, l4);
    *(HF4*)&hi[base] = h4;
    *(HF4*)&lo[base] = l4;
}

// ---------------------------------------------------------------------------
// Scores GEMM: 3-product fp16 (hh+lh+hl), CTA 128x128, KC=32, 2-stage.
// Epilogue: e = exp(v-SHIFT), row/col sums via atomicAdd, writes e.
// ---------------------------------------------------------------------------
#define KC 32
#define AP 40            // [M,K]-tile pitch in halves (80B rows)
#define BP 136           // [K,N]-tile pitch in halves (272B rows)
#define TILE_MK (128 * AP * 2)   // 10240 bytes
#define S_STAGE (4 * TILE_MK)    // 40960 bytes (Ahi,Alo,Bhi,Blo)

__global__ __launch_bounds__(256, 2)
void k_scores(const __half* __restrict__ Ahi, const __half* __restrict__ Alo,
              const __half* __restrict__ Bhi, const __half* __restrict__ Blo,
              float* __restrict__ C,
              float* __restrict__ rsum, float* __restrict__ csum) {
    extern __shared__ char sm[];
    const uint32_t sbase = smem_u32(sm);

    int tid = threadIdx.x;
    int wid = tid >> 5;
    int wm  = wid & 3;
    int wn  = wid >> 2;
    int b   = blockIdx.z;
    int m0  = blockIdx.y * 128;
    int n0  = blockIdx.x * 128;

    const __half* Ah = Ahi + (size_t)b * Ll * Dd + (size_t)m0 * Dd;
    const __half* Al = Alo + (size_t)b * Ll * Dd + (size_t)m0 * Dd;
    const __half* Bh = Bhi + (size_t)b * Ll * Dd + (size_t)n0 * Dd;
    const __half* Bl = Blo + (size_t)b * Ll * Dd + (size_t)n0 * Dd;

    int arow = tid >> 2;            // 0..63 (x2 -> 128 rows)
    int ac16 = (tid & 3) * 8;       // covers KC=32 halves

    auto load_stage = [&](int st, int k0) {
        uint32_t s = sbase + st * S_STAGE;
#pragma unroll
        for (int h = 0; h < 2; ++h) {
            int r = arow + h * 64;
            uint32_t d = s + r * (AP * 2) + ac16 * 2;
            cp16(d,                Ah + (size_t)r * Dd + k0 + ac16);
            cp16(d + TILE_MK,      Al + (size_t)r * Dd + k0 + ac16);
            cp16(d + 2 * TILE_MK,  Bh + (size_t)r * Dd + k0 + ac16);
            cp16(d + 3 * TILE_MK,  Bl + (size_t)r * Dd + k0 + ac16);
        }
    };

    wmma::fragment<wmma::accumulator, 16, 16, 16, float> acc[2][4];
#pragma unroll
    for (int i = 0; i < 2; ++i)
#pragma unroll
        for (int j = 0; j < 4; ++j)
            wmma::fill_fragment(acc[i][j], 0.0f);

    const int NK = Dd / KC;
    load_stage(0, 0);
    CP_COMMIT();

    for (int it = 0; it < NK; ++it) {
        if (it + 1 < NK) {
            load_stage((it + 1) & 1, (it + 1) * KC);
            CP_COMMIT();
            CP_WAIT(1);
        } else {
            CP_WAIT(0);
        }
        __syncthreads();

        const __half* sA0 = (const __half*)(sm + (it & 1) * S_STAGE);
        const __half* sAl = sA0 + TILE_MK / 2;
        const __half* sB0 = sA0 + TILE_MK;
        const __half* sBl = sA0 + 3 * TILE_MK / 2;

#pragma unroll
        for (int ks = 0; ks < KC / 16; ++ks) {
            wmma::fragment<wmma::matrix_a, 16, 16, 16, __half, wmma::row_major> ah[2], al[2];
#pragma unroll
            for (int fi = 0; fi < 2; ++fi) {
                int ro = (wm * 32 + fi * 16) * AP + ks * 16;
                wmma::load_matrix_sync(ah[fi], &sA0[ro], AP);
                wmma::load_matrix_sync(al[fi], &sAl[ro], AP);
            }
#pragma unroll
            for (int fj = 0; fj < 4; ++fj) {
                wmma::fragment<wmma::matrix_b, 16, 16, 16, __half, wmma::col_major> bh, bl;
                int ro = (wn * 64 + fj * 16) * AP + ks * 16;
                wmma::load_matrix_sync(bh, &sB0[ro], AP);
                wmma::load_matrix_sync(bl, &sBl[ro], AP);
#pragma unroll
                for (int fi = 0; fi < 2; ++fi) {
                    wmma::mma_sync(acc[fi][fj], ah[fi], bh, acc[fi][fj]);
                    wmma::mma_sync(acc[fi][fj], al[fi], bh, acc[fi][fj]);
                    wmma::mma_sync(acc[fi][fj], ah[fi], bl, acc[fi][fj]);
                }
            }
        }
        __syncthreads();
    }

    // --- Epilogue: exp + row/col sums + e write ---
    float* Cb = C + (size_t)b * Ll * Ll;
    float* Sf = (float*)sm;   // 128 x 132 fp32 = 67584 B
#pragma unroll
    for (int fi = 0; fi < 2; ++fi)
#pragma unroll
        for (int fj = 0; fj < 4; ++fj) {
            int lr = wm * 32 + fi * 16;
            int lc = wn * 64 + fj * 16;
            wmma::store_matrix_sync(&Sf[lr * 132 + lc], acc[fi][fj], 132,
                                    wmma::mem_row_major);
        }
    __syncthreads();

    {   // row pass: exp in place + row sums
        int r = tid >> 1, half = tid & 1;
        float* row = Sf + r * 132 + half * 64;
        float s = 0.f;
#pragma unroll 8
        for (int c = 0; c < 64; ++c) {
            float e = __expf(row[c] - SHIFT);
            row[c] = e;
            s += e;
        }
        s += __shfl_xor_sync(0xffffffffu, s, 1);
        if (!half) atomicAdd(&rsum[(size_t)b * Ll + m0 + r], s);
    }
    __syncthreads();

    {   // col pass
        int c = tid >> 1, half = tid & 1;
        float s = 0.f;
#pragma unroll 8
        for (int r = 0; r < 64; ++r)
            s += Sf[(half * 64 + r) * 132 + c];
        s += __shfl_xor_sync(0xffffffffu, s, 1);
        if (!half) atomicAdd(&csum[(size_t)b * Ll + n0 + c], s);
    }
    __syncthreads();

#pragma unroll 4
    for (int it2 = 0; it2 < 16; ++it2) {
        int q  = tid + it2 * 256;
        int ii = q >> 5;
        int c4 = (q & 31) * 4;
        float4 v = *(float4*)&Sf[ii * 132 + c4];
        *(float4*)&Cb[(size_t)(m0 + ii) * Ll + n0 + c4] = v;
    }
}

// ---------------------------------------------------------------------------
// Invert sums in place
// ---------------------------------------------------------------------------
__global__ __launch_bounds__(256)
void k_invert(float* __restrict__ rsum, float* __restrict__ csum) {
    int i = blockIdx.x * 256 + threadIdx.x;
    float* p = (i < Bb * Ll) ? (rsum + i) : (csum + i - Bb * Ll);
    *p = 1.0f / *p;
}

// ---------------------------------------------------------------------------
// Merged output GEMMs, normalization fused into the A-loader.
// KC2=32, A: e (fp32) LDG -> scale -> fp16 smem; B: in-hi fp16 cp.async.
//   A_COL=true  (outA): out[j,d] = sum_i (e[i,j]*csinv[j]) * in1[i,d]
//                       A-tile [K=32 i-rows x 128 j-cols], col_major frags
//   A_COL=false (outB): out[i,d] = sum_j (e[i,j]*rsinv[i]) * in2[j,d]
//                       A-tile [128 i-rows x K=32 j-cols], row_major frags
// ---------------------------------------------------------------------------
#define KC2 32
#define A16_COL (KC2 * BP * 2)    // 8704  bytes: 32 x 128 halves (pitch 136)
#define A16_ROW (128 * AP * 2)    // 10240 bytes: 128 x 32 halves (pitch 40)
#define B16T    (KC2 * BP * 2)    // 8704  bytes: 32 x 128 halves

template <bool A_COL>
__device__ __forceinline__
void out_body(const float* __restrict__ E, const __half* __restrict__ IN,
              const float* __restrict__ inv, float* __restrict__ out,
              int b, char* sm) {
    const uint32_t sbase = smem_u32(sm);
    constexpr int ATILE = A_COL ? A16_COL : A16_ROW;

    int tid = threadIdx.x;
    int wid = tid >> 5;
    int wm  = wid & 3;
    int wn  = wid >> 2;
    int m0  = blockIdx.y * 128;
    int n0  = blockIdx.x * 128;

    const float*  Eb  = E  + (size_t)b * Ll * Ll;
    const __half* INb = IN + (size_t)b * Ll * Dd + n0;

    // --- prologue: loop-invariant scale values ---
    float4 csv;            // outA: per-thread 4 column scales
    float  rsv[4];         // outB: per-thread 4 row scales
    if (A_COL) {
        csv = *(const float4*)&inv[(size_t)b * Ll + m0 + (tid & 31) * 4];
    } else {
#pragma unroll
        for (int l = 0; l < 4; ++l)
            rsv[l] = inv[(size_t)b * Ll + m0 + l * 32 + (tid >> 3)];
    }

    // B cp.async map
    int brow = tid >> 4;            // 0..15 (x2 -> 32 rows)
    int bc16 = (tid & 15) * 8;      // covers 128 cols

    auto cp_B = [&](int st, int k0) {
        uint32_t s = sbase + 2 * ATILE + st * B16T;
#pragma unroll
        for (int h = 0; h < 2; ++h) {
            int r = brow + h * 16;
            cp16(s + r * (BP * 2) + bc16 * 2, INb + (size_t)(k0 + r) * Dd + bc16);
        }
    };

    // A LDG: 4 x float4 per thread per stage (fully coalesced rows)
    auto ldg_A = [&](int k0, float4 (&r)[4]) {
#pragma unroll
        for (int l = 0; l < 4; ++l) {
            if (A_COL) {
                int row = l * 8 + (tid >> 5);           // i
                int c   = (tid & 31) * 4;               // j
                r[l] = *(const float4*)&Eb[(size_t)(k0 + row) * Ll + m0 + c];
            } else {
                int row = l * 32 + (tid >> 3);          // i
                int c   = (tid & 7) * 4;                // j
                r[l] = *(const float4*)&Eb[(size_t)(m0 + row) * Ll + k0 + c];
            }
        }
    };

    // scale + convert + STS into fp16 A-tile
    auto cvt_A = [&](int st, float4 (&r)[4]) {
        __half* A16 = (__half*)(sm + st * ATILE);
#pragma unroll
        for (int l = 0; l < 4; ++l) {
            uint2 h;
            if (A_COL) {
                int row = l * 8 + (tid >> 5);
                int c   = (tid & 31) * 4;
                h.x = pack2(r[l].x * csv.x, r[l].y * csv.y);
                h.y = pack2(r[l].z * csv.z, r[l].w * csv.w);
                *(uint2*)&A16[row * BP + c] = h;
            } else {
                int row = l * 32 + (tid >> 3);
                int c   = (tid & 7) * 4;
                float s = rsv[l];
                h.x = pack2(r[l].x * s, r[l].y * s);
                h.y = pack2(r[l].z * s, r[l].w * s);
                *(uint2*)&A16[row * AP + c] = h;
            }
        }
    };

    wmma::fragment<wmma::accumulator, 16, 16, 16, float> acc[2][4];
#pragma unroll
    for (int i = 0; i < 2; ++i)
#pragma unroll
        for (int j = 0; j < 4; ++j)
            wmma::fill_fragment(acc[i][j], 0.0f);

    const int NK = Ll / KC2;   // 32
    float4 r[4];

    // prologue: stage 0 A (convert immediately), B(0); prefetch A(1)
    cp_B(0, 0);
    CP_COMMIT();
    ldg_A(0, r);
    cvt_A(0, r);
    ldg_A(KC2, r);

    for (int it = 0; it < NK; ++it) {
        if (it + 1 < NK) {
            cp_B((it + 1) & 1, (it + 1) * KC2);
            CP_COMMIT();
            CP_WAIT(1);
        } else {
            CP_WAIT(0);
        }
        __syncthreads();

        // compute(it)
        {
            const __half* sA0 = (const __half*)(sm + (it & 1) * ATILE);
            const __half* sB0 = (const __half*)(sm + 2 * ATILE + (it & 1) * B16T);
#pragma unroll
            for (int ks = 0; ks < KC2 / 16; ++ks) {
                if constexpr (A_COL) {
                    wmma::fragment<wmma::matrix_a, 16, 16, 16, __half, wmma::col_major> ah[2];
#pragma unroll
                    for (int fi = 0; fi < 2; ++fi) {
                        int ro = (ks * 16) * BP + wm * 32 + fi * 16;
                        wmma::load_matrix_sync(ah[fi], &sA0[ro], BP);
                    }
#pragma unroll
                    for (int fj = 0; fj < 4; ++fj) {
                        wmma::fragment<wmma::matrix_b, 16, 16, 16, __half, wmma::row_major> bh;
                        int ro = (ks * 16) * BP + wn * 64 + fj * 16;
                        wmma::load_matrix_sync(bh, &sB0[ro], BP);
#pragma unroll
                        for (int fi = 0; fi < 2; ++fi)
                            wmma::mma_sync(acc[fi][fj], ah[fi], bh, acc[fi][fj]);
                    }
                } else {
                    wmma::fragment<wmma::matrix_a, 16, 16, 16, __half, wmma::row_major> ah[2];
#pragma unroll
                    for (int fi = 0; fi < 2; ++fi) {
                        int ro = (wm * 32 + fi * 16) * AP + ks * 16;
                        wmma::load_matrix_sync(ah[fi], &sA0[ro], AP);
                    }
#pragma unroll
                    for (int fj = 0; fj < 4; ++fj) {
                        wmma::fragment<wmma::matrix_b, 16, 16, 16, __half, wmma::row_major> bh;
                        int ro = (ks * 16) * BP + wn * 64 + fj * 16;
                        wmma::load_matrix_sync(bh, &sB0[ro], BP);
#pragma unroll
                        for (int fi = 0; fi < 2; ++fi)
                            wmma::mma_sync(acc[fi][fj], ah[fi], bh, acc[fi][fj]);
                    }
                }
            }
        }

        // stage it+1: convert held regs; prefetch it+2
        if (it + 1 < NK) {
            cvt_A((it + 1) & 1, r);
            if (it + 2 < NK) ldg_A((it + 2) * KC2, r);
        }
        __syncthreads();
    }

    float* Cb = out + (size_t)b * Ll * Dd;
#pragma unroll
    for (int fi = 0; fi < 2; ++fi)
#pragma unroll
        for (int fj = 0; fj < 4; ++fj) {
            int gr = m0 + wm * 32 + fi * 16;
            int gc = n0 + wn * 64 + fj * 16;
            wmma::store_matrix_sync(&Cb[(size_t)gr * Dd + gc], acc[fi][fj], Dd,
                                    wmma::mem_row_major);
        }
}

__global__ __launch_bounds__(256, 2)
void k_out(const float* __restrict__ eatt,
           const float* __restrict__ rsinv, const float* __restrict__ csinv,
           const __half* __restrict__ i1h, const __half* __restrict__ i2h,
           float* __restrict__ out) {
    extern __shared__ char sm[];
    int z = blockIdx.z;
    if (z < Bb) out_body<true >(eatt, i1h, csinv, out, z, sm);
    else        out_body<false>(eatt, i2h, rsinv, out + (size_t)Bb * Ll * Dd, z - Bb, sm);
}

// ---------------------------------------------------------------------------
extern "C" void kernel_launch(void* const* d_in, const int* in_sizes, int n_in,
                              void* d_out, int out_size) {
    const float* in1 = (const float*)d_in[0];
    const float* in2 = (const float*)d_in[1];
    float* out = (float*)d_out;

    const int SMEM_SCORES = 2 * S_STAGE;                 // 81920
    const int SMEM_OUT    = 2 * A16_ROW + 2 * B16T;      // 37888 (row variant max)
    cudaFuncSetAttribute(k_scores, cudaFuncAttributeMaxDynamicSharedMemorySize, SMEM_SCORES);
    cudaFuncSetAttribute(k_out,    cudaFuncAttributeMaxDynamicSharedMemorySize, SMEM_OUT);

    float *eatt, *rsum, *csum;
    __half *i1h, *i1l, *i2h, *i2l;
    cudaGetSymbolAddress((void**)&eatt, g_eatt);
    cudaGetSymbolAddress((void**)&rsum, g_rsum);
    cudaGetSymbolAddress((void**)&csum, g_csum);
    cudaGetSymbolAddress((void**)&i1h,  g_in1hi);
    cudaGetSymbolAddress((void**)&i1l,  g_in1lo);
    cudaGetSymbolAddress((void**)&i2h,  g_in2hi);
    cudaGetSymbolAddress((void**)&i2l,  g_in2lo);

    // 1) split inputs to fp16 hi/lo (+ zero rsum/csum)
    int sblk = (int)(((size_t)Bb * Ll * Dd) / (256 * 4));
    k_split2<<<dim3(sblk, 2), 256>>>(in1, in2, i1h, i1l, i2h, i2l, rsum, csum);

    // 2) scores GEMM (3 products) + fused exp/row-sum/col-sum epilogue -> eatt
    k_scores<<<dim3(Ll / 128, Ll / 128, Bb), 256, SMEM_SCORES>>>(
        i1h, i1l, i2h, i2l, eatt, rsum, csum);

    // 3) invert sums
    k_invert<<<(2 * Bb * Ll) / 256, 256>>>(rsum, csum);

    // 4) merged output GEMMs with fused normalization (reads eatt directly)
    k_out<<<dim3(Dd / 128, Ll / 128, 2 * Bb), 256, SMEM_OUT>>>(
        eatt, rsum, csum, i1h, i2h, out);
}